// round 1
// baseline (speedup 1.0000x reference)
#include <cuda_runtime.h>
#include <math.h>

// Problem constants: B=8, S=1024, C=512, H=8, DH=64
namespace {
constexpr int kB  = 8;
constexpr int kS  = 1024;
constexpr int kC  = 512;
constexpr int kH  = 8;
constexpr int kDH = 64;
constexpr int kM  = kB * kS;   // 8192 rows
}

// Scratch (allocation-free: device globals). 4 x 16 MB.
__device__ float g_q[kM * kC];
__device__ float g_k[kM * kC];
__device__ float g_v[kM * kC];
__device__ float g_ctx[kM * kC];

// ---------------------------------------------------------------------------
// GEMM: out[m,n] = sum_k X[m,k] * W[n,k] + bias[n] (+ skip[m,n])
// M=8192, N=512, K=512. BM=BN=128, BK=8, 256 threads, 8x8 per thread.
// Both operands are row-major along K ("NT" layout) -> contiguous loads.
// ---------------------------------------------------------------------------
template <bool ADD_SKIP>
__global__ void __launch_bounds__(256, 2)
gemm_nt_kernel(const float* __restrict__ X, const float* __restrict__ W,
               const float* __restrict__ bias, const float* __restrict__ skip,
               float* __restrict__ out)
{
    constexpr int K = kC;
    constexpr int N = kC;
    __shared__ __align__(16) float As[8][132];   // [k][m], pitch 132 kills STS conflicts
    __shared__ __align__(16) float Bs[8][132];   // [k][n]

    const int tid = threadIdx.x;
    const int m0  = blockIdx.y * 128;
    const int n0  = blockIdx.x * 128;
    const int lr  = tid >> 1;           // 0..127 (tile row)
    const int lc  = (tid & 1) * 4;      // 0 or 4 (k offset)
    const int tx  = tid & 15;
    const int ty  = tid >> 4;

    const float* Ap = X + (size_t)(m0 + lr) * K + lc;
    const float* Bp = W + (size_t)(n0 + lr) * K + lc;

    float acc[8][8];
#pragma unroll
    for (int i = 0; i < 8; i++)
#pragma unroll
        for (int j = 0; j < 8; j++) acc[i][j] = 0.f;

    // prefetch first k-slab
    float4 a = *(const float4*)Ap;
    float4 b = *(const float4*)Bp;

    for (int k0 = 0; k0 < K; k0 += 8) {
        __syncthreads();
        As[lc + 0][lr] = a.x; As[lc + 1][lr] = a.y;
        As[lc + 2][lr] = a.z; As[lc + 3][lr] = a.w;
        Bs[lc + 0][lr] = b.x; Bs[lc + 1][lr] = b.y;
        Bs[lc + 2][lr] = b.z; Bs[lc + 3][lr] = b.w;
        __syncthreads();

        if (k0 + 8 < K) {   // prefetch next slab, overlapped with compute below
            Ap += 8; Bp += 8;
            a = *(const float4*)Ap;
            b = *(const float4*)Bp;
        }

#pragma unroll
        for (int kk = 0; kk < 8; kk++) {
            float af[8], bf[8];
            *(float4*)&af[0] = *(const float4*)&As[kk][ty * 4];
            *(float4*)&af[4] = *(const float4*)&As[kk][64 + ty * 4];
            *(float4*)&bf[0] = *(const float4*)&Bs[kk][tx * 4];
            *(float4*)&bf[4] = *(const float4*)&Bs[kk][64 + tx * 4];
#pragma unroll
            for (int i = 0; i < 8; i++)
#pragma unroll
                for (int j = 0; j < 8; j++)
                    acc[i][j] = fmaf(af[i], bf[j], acc[i][j]);
        }
    }

    // epilogue: bias (+skip), vectorized stores
#pragma unroll
    for (int i = 0; i < 8; i++) {
        const int m = m0 + ((i < 4) ? (ty * 4 + i) : (64 + ty * 4 + (i - 4)));
#pragma unroll
        for (int jj = 0; jj < 2; jj++) {
            const int n = n0 + jj * 64 + tx * 4;
            float4 bb = *(const float4*)&bias[n];
            float4 r;
            r.x = acc[i][jj * 4 + 0] + bb.x;
            r.y = acc[i][jj * 4 + 1] + bb.y;
            r.z = acc[i][jj * 4 + 2] + bb.z;
            r.w = acc[i][jj * 4 + 3] + bb.w;
            if (ADD_SKIP) {
                float4 sk = *(const float4*)&skip[(size_t)m * N + n];
                r.x += sk.x; r.y += sk.y; r.z += sk.z; r.w += sk.w;
            }
            *(float4*)&out[(size_t)m * N + n] = r;
        }
    }
}

// ---------------------------------------------------------------------------
// Flash attention, fp32. One CTA = one (b, h, 64-query tile).
// smem: Qs/Ks stored transposed [d][row] pitch 65 (<=2-way LDS conflicts),
// Vs natural [k][d] pitch 65, Ps [q][k] pitch 65.  4 * 64*65*4 = 66560 B dyn.
// Thread map: 16x16, each thread owns a 4(q) x 4(k or d) microtile.
// Row reductions across the 16 tx-lanes via shfl_xor (1,2,4,8).
// ---------------------------------------------------------------------------
__global__ void __launch_bounds__(256)
attn_kernel()
{
    constexpr int SD = 65;
    extern __shared__ float sm[];
    float* Qs  = sm;                 // [d][q]
    float* Ksm = Qs  + 64 * SD;      // [d][k]
    float* Vsm = Ksm + 64 * SD;      // [k][d]
    float* Ps  = Vsm + 64 * SD;      // [q][k]

    const int tid = threadIdx.x;
    const int tx  = tid & 15;
    const int ty  = tid >> 4;
    const int b   = blockIdx.z;
    const int h   = blockIdx.y;
    const int q0  = blockIdx.x * 64;

    const float* Qg = g_q + (size_t)(b * kS + q0) * kC + h * kDH;
    const float* Kg = g_k + (size_t)(b * kS) * kC + h * kDH;
    const float* Vg = g_v + (size_t)(b * kS) * kC + h * kDH;

    // load Q tile transposed
#pragma unroll
    for (int r = 0; r < 4; r++) {
        int idx = tid + r * 256;          // 0..1023 float4s
        int row = idx >> 4;               // 0..63
        int c4  = (idx & 15) * 4;         // 0..60
        float4 qv = *(const float4*)(Qg + (size_t)row * kC + c4);
        Qs[(c4 + 0) * SD + row] = qv.x;
        Qs[(c4 + 1) * SD + row] = qv.y;
        Qs[(c4 + 2) * SD + row] = qv.z;
        Qs[(c4 + 3) * SD + row] = qv.w;
    }

    float m_i[4], l_i[4], accO[4][4];
#pragma unroll
    for (int i = 0; i < 4; i++) {
        m_i[i] = -INFINITY;
        l_i[i] = 0.f;
#pragma unroll
        for (int j = 0; j < 4; j++) accO[i][j] = 0.f;
    }
    const float cexp = 0.125f * 1.4426950408889634f;  // scale * log2(e)

    for (int kt = 0; kt < kS; kt += 64) {
        __syncthreads();   // prev iter done with Ks/Vs (and Q store visible)
#pragma unroll
        for (int r = 0; r < 4; r++) {
            int idx = tid + r * 256;
            int row = idx >> 4;
            int c4  = (idx & 15) * 4;
            float4 kv = *(const float4*)(Kg + (size_t)(kt + row) * kC + c4);
            Ksm[(c4 + 0) * SD + row] = kv.x;
            Ksm[(c4 + 1) * SD + row] = kv.y;
            Ksm[(c4 + 2) * SD + row] = kv.z;
            Ksm[(c4 + 3) * SD + row] = kv.w;
            float4 vv = *(const float4*)(Vg + (size_t)(kt + row) * kC + c4);
            Vsm[row * SD + c4 + 0] = vv.x;
            Vsm[row * SD + c4 + 1] = vv.y;
            Vsm[row * SD + c4 + 2] = vv.z;
            Vsm[row * SD + c4 + 3] = vv.w;
        }
        __syncthreads();

        // S = Q K^T   (raw scores; scale folded into exp2)
        float s[4][4];
#pragma unroll
        for (int i = 0; i < 4; i++)
#pragma unroll
            for (int j = 0; j < 4; j++) s[i][j] = 0.f;

#pragma unroll 8
        for (int d = 0; d < 64; d++) {
            float qf[4], kf[4];
#pragma unroll
            for (int i = 0; i < 4; i++) qf[i] = Qs[d * SD + ty * 4 + i];
#pragma unroll
            for (int j = 0; j < 4; j++) kf[j] = Ksm[d * SD + tx * 4 + j];
#pragma unroll
            for (int i = 0; i < 4; i++)
#pragma unroll
                for (int j = 0; j < 4; j++)
                    s[i][j] = fmaf(qf[i], kf[j], s[i][j]);
        }

        // online softmax update per row
#pragma unroll
        for (int i = 0; i < 4; i++) {
            float rm = fmaxf(fmaxf(s[i][0], s[i][1]), fmaxf(s[i][2], s[i][3]));
            rm = fmaxf(rm, __shfl_xor_sync(0xffffffffu, rm, 1));
            rm = fmaxf(rm, __shfl_xor_sync(0xffffffffu, rm, 2));
            rm = fmaxf(rm, __shfl_xor_sync(0xffffffffu, rm, 4));
            rm = fmaxf(rm, __shfl_xor_sync(0xffffffffu, rm, 8));
            float m_new = fmaxf(m_i[i], rm);
            float alpha = exp2f((m_i[i] - m_new) * cexp);
            float rs = 0.f;
#pragma unroll
            for (int j = 0; j < 4; j++) {
                s[i][j] = exp2f((s[i][j] - m_new) * cexp);
                rs += s[i][j];
            }
            rs += __shfl_xor_sync(0xffffffffu, rs, 1);
            rs += __shfl_xor_sync(0xffffffffu, rs, 2);
            rs += __shfl_xor_sync(0xffffffffu, rs, 4);
            rs += __shfl_xor_sync(0xffffffffu, rs, 8);
            l_i[i] = l_i[i] * alpha + rs;
            m_i[i] = m_new;
#pragma unroll
            for (int j = 0; j < 4; j++) accO[i][j] *= alpha;
        }

        // P -> smem
#pragma unroll
        for (int i = 0; i < 4; i++)
#pragma unroll
            for (int j = 0; j < 4; j++)
                Ps[(ty * 4 + i) * SD + tx * 4 + j] = s[i][j];
        __syncthreads();

        // O += P V
#pragma unroll 8
        for (int kk2 = 0; kk2 < 64; kk2++) {
            float pf[4], vf[4];
#pragma unroll
            for (int i = 0; i < 4; i++) pf[i] = Ps[(ty * 4 + i) * SD + kk2];
#pragma unroll
            for (int j = 0; j < 4; j++) vf[j] = Vsm[kk2 * SD + tx * 4 + j];
#pragma unroll
            for (int i = 0; i < 4; i++)
#pragma unroll
                for (int j = 0; j < 4; j++)
                    accO[i][j] = fmaf(pf[i], vf[j], accO[i][j]);
        }
    }

    // normalize + write ctx
    float* Og = g_ctx + (size_t)(b * kS + q0) * kC + h * kDH;
#pragma unroll
    for (int i = 0; i < 4; i++) {
        float inv = 1.f / l_i[i];
        int q = ty * 4 + i;
#pragma unroll
        for (int j = 0; j < 4; j++)
            Og[(size_t)q * kC + tx * 4 + j] = accO[i][j] * inv;
    }
}

// ---------------------------------------------------------------------------
// Launch: QKV projections -> flash attention -> output projection (+bias+skip)
// Inputs (metadata order): x, skip, Wq, bq, Wk, bk, Wv, bv, Wo, bo. Output f32.
// ---------------------------------------------------------------------------
extern "C" void kernel_launch(void* const* d_in, const int* in_sizes, int n_in,
                              void* d_out, int out_size)
{
    (void)in_sizes; (void)n_in; (void)out_size;
    const float* x    = (const float*)d_in[0];
    const float* skip = (const float*)d_in[1];
    const float* Wq   = (const float*)d_in[2];
    const float* bq   = (const float*)d_in[3];
    const float* Wk   = (const float*)d_in[4];
    const float* bk   = (const float*)d_in[5];
    const float* Wv   = (const float*)d_in[6];
    const float* bv   = (const float*)d_in[7];
    const float* Wo   = (const float*)d_in[8];
    const float* bo   = (const float*)d_in[9];
    float* out = (float*)d_out;

    float *qb, *kb, *vb, *ctxb;
    cudaGetSymbolAddress((void**)&qb,   g_q);
    cudaGetSymbolAddress((void**)&kb,   g_k);
    cudaGetSymbolAddress((void**)&vb,   g_v);
    cudaGetSymbolAddress((void**)&ctxb, g_ctx);

    constexpr int kAttnSmem = 4 * 64 * 65 * 4;   // 66560 B
    cudaFuncSetAttribute(attn_kernel, cudaFuncAttributeMaxDynamicSharedMemorySize,
                         kAttnSmem);

    dim3 gemm_grid(kC / 128, kM / 128);   // (4, 64)
    gemm_nt_kernel<false><<<gemm_grid, 256>>>(x, Wq, bq, nullptr, qb);
    gemm_nt_kernel<false><<<gemm_grid, 256>>>(x, Wk, bk, nullptr, kb);
    gemm_nt_kernel<false><<<gemm_grid, 256>>>(x, Wv, bv, nullptr, vb);

    attn_kernel<<<dim3(kS / 64, kH, kB), 256, kAttnSmem>>>();

    gemm_nt_kernel<true><<<gemm_grid, 256>>>(ctxb, Wo, bo, skip, out);
}

// round 3
// speedup vs baseline: 2.4004x; 2.4004x over previous
#include <cuda_runtime.h>
#include <math.h>
#include <stdint.h>

// Problem constants: B=8, S=1024, C=512, H=8, DH=64
namespace {
constexpr int kB  = 8;
constexpr int kS  = 1024;
constexpr int kC  = 512;
constexpr int kH  = 8;
constexpr int kDH = 64;
constexpr int kM  = kB * kS;   // 8192 rows
}

// Scratch (allocation-free: device globals). 4 x 16 MB.
__device__ float g_q[kM * kC];
__device__ float g_k[kM * kC];
__device__ float g_v[kM * kC];
__device__ float g_ctx[kM * kC];

// ===========================================================================
// Legacy tensor-core helpers (work on base sm_103 target; tcgen05 does NOT)
// ===========================================================================
__device__ __forceinline__ uint32_t smem_u32(const void* p) {
    uint32_t a;
    asm("{ .reg .u64 t; cvta.to.shared.u64 t, %1; cvt.u32.u64 %0, t; }"
        : "=r"(a) : "l"(p));
    return a;
}

__device__ __forceinline__ uint32_t f2tf32(float f) {
    uint32_t u;
    asm("cvt.rna.tf32.f32 %0, %1;" : "=r"(u) : "f"(f));
    return u;
}

__device__ __forceinline__ void ldmatrix_x4(uint32_t& r0, uint32_t& r1,
                                            uint32_t& r2, uint32_t& r3,
                                            uint32_t addr) {
    asm volatile("ldmatrix.sync.aligned.m8n8.x4.shared.b16 {%0,%1,%2,%3}, [%4];"
                 : "=r"(r0), "=r"(r1), "=r"(r2), "=r"(r3) : "r"(addr));
}

// D(16x8) += A(16x8) * B(8x8), tf32 inputs, fp32 accumulate.
__device__ __forceinline__ void mma_tf32(float* c, uint32_t a0, uint32_t a1,
                                         uint32_t a2, uint32_t a3,
                                         uint32_t b0, uint32_t b1) {
    asm volatile(
        "mma.sync.aligned.m16n8k8.row.col.f32.tf32.tf32.f32 "
        "{%0,%1,%2,%3}, {%4,%5,%6,%7}, {%8,%9}, {%0,%1,%2,%3};"
        : "+f"(c[0]), "+f"(c[1]), "+f"(c[2]), "+f"(c[3])
        : "r"(a0), "r"(a1), "r"(a2), "r"(a3), "r"(b0), "r"(b1));
}

// ===========================================================================
// tf32 mma.sync GEMM: out[m,n] = sum_k X[m,k]*W[n,k] + bias[n] (+skip[m,n])
// M=8192, N=512, K=512. CTA 128x128, BK=16, 8 warps each 32(m) x 64(n).
// smem rows pitch 20 floats (80 B): 16B-aligned rows, conflict-free ldmatrix
// (20*r mod 32 hits 8 distinct 4-bank groups for r=0..7).
// ===========================================================================
namespace { constexpr int PK = 20; }

template <bool ADD_SKIP>
__global__ void __launch_bounds__(256)
gemm_tf32_kernel(const float* __restrict__ X, const float* __restrict__ W,
                 const float* __restrict__ bias, const float* __restrict__ skip,
                 float* __restrict__ out)
{
    __shared__ __align__(16) uint32_t sA[128 * PK];
    __shared__ __align__(16) uint32_t sB[128 * PK];

    const int tid = threadIdx.x;
    const int lid = tid & 31;
    const int wid = tid >> 5;
    const int m0  = blockIdx.y * 128;
    const int n0  = blockIdx.x * 128;
    const int wm  = (wid >> 1) * 32;   // warp m-offset within tile
    const int wn  = (wid & 1) * 64;    // warp n-offset within tile

    // loader coords: 2 float4 per matrix per slab
    const int lrow = tid >> 2;         // 0..63
    const int lc4  = (tid & 3) * 4;    // 0,4,8,12

    const float* Ap = X + (size_t)(m0 + lrow) * kC + lc4;
    const float* Bp = W + (size_t)(n0 + lrow) * kC + lc4;

    // per-thread ldmatrix smem byte offsets (slab-invariant)
    const uint32_t sAu = smem_u32(sA);
    const uint32_t sBu = smem_u32(sB);
    uint32_t a_addr[2], b_addr[4];
#pragma unroll
    for (int t = 0; t < 2; t++)
        a_addr[t] = sAu + (((wm + 16 * t + (lid & 15)) * PK + ((lid >> 4) << 2)) << 2);
#pragma unroll
    for (int jj = 0; jj < 4; jj++)
        b_addr[jj] = sBu + (((wn + 16 * jj + ((lid >> 4) << 3) + (lid & 7)) * PK
                             + (((lid >> 3) & 1) << 2)) << 2);

    float acc[2][8][4];
#pragma unroll
    for (int t = 0; t < 2; t++)
#pragma unroll
        for (int j = 0; j < 8; j++)
#pragma unroll
            for (int c = 0; c < 4; c++) acc[t][j][c] = 0.f;

    // prefetch slab 0
    float4 pa0 = *(const float4*)Ap;
    float4 pa1 = *(const float4*)(Ap + (size_t)64 * kC);
    float4 pb0 = *(const float4*)Bp;
    float4 pb1 = *(const float4*)(Bp + (size_t)64 * kC);

#pragma unroll 1
    for (int s = 0; s < kC / 16; s++) {
        __syncthreads();
        {
            uint32_t* da = &sA[lrow * PK + lc4];
            da[0] = f2tf32(pa0.x); da[1] = f2tf32(pa0.y);
            da[2] = f2tf32(pa0.z); da[3] = f2tf32(pa0.w);
            uint32_t* da2 = da + 64 * PK;
            da2[0] = f2tf32(pa1.x); da2[1] = f2tf32(pa1.y);
            da2[2] = f2tf32(pa1.z); da2[3] = f2tf32(pa1.w);
            uint32_t* db = &sB[lrow * PK + lc4];
            db[0] = f2tf32(pb0.x); db[1] = f2tf32(pb0.y);
            db[2] = f2tf32(pb0.z); db[3] = f2tf32(pb0.w);
            uint32_t* db2 = db + 64 * PK;
            db2[0] = f2tf32(pb1.x); db2[1] = f2tf32(pb1.y);
            db2[2] = f2tf32(pb1.z); db2[3] = f2tf32(pb1.w);
        }
        __syncthreads();

        if (s + 1 < kC / 16) {
            Ap += 16; Bp += 16;
            pa0 = *(const float4*)Ap;
            pa1 = *(const float4*)(Ap + (size_t)64 * kC);
            pb0 = *(const float4*)Bp;
            pb1 = *(const float4*)(Bp + (size_t)64 * kC);
        }

#pragma unroll
        for (int ks = 0; ks < 2; ks++) {
            const uint32_t koff = ks * 32;   // 8 floats = 32 bytes
            uint32_t a[2][4];
#pragma unroll
            for (int t = 0; t < 2; t++)
                ldmatrix_x4(a[t][0], a[t][1], a[t][2], a[t][3], a_addr[t] + koff);
            uint32_t b[8][2];
#pragma unroll
            for (int jj = 0; jj < 4; jj++) {
                uint32_t r0, r1, r2, r3;
                ldmatrix_x4(r0, r1, r2, r3, b_addr[jj] + koff);
                b[2 * jj][0] = r0;  b[2 * jj][1] = r1;
                b[2 * jj + 1][0] = r2;  b[2 * jj + 1][1] = r3;
            }
#pragma unroll
            for (int t = 0; t < 2; t++)
#pragma unroll
                for (int j = 0; j < 8; j++)
                    mma_tf32(acc[t][j], a[t][0], a[t][1], a[t][2], a[t][3],
                             b[j][0], b[j][1]);
        }
    }

    // Epilogue: c0,c1 -> (r0, col..col+1), c2,c3 -> (r0+8, ...)
    const int g  = lid >> 2;
    const int cp = (lid & 3) * 2;
#pragma unroll
    for (int t = 0; t < 2; t++) {
        const int r0 = m0 + wm + 16 * t + g;
#pragma unroll
        for (int j = 0; j < 8; j++) {
            const int n = n0 + wn + 8 * j + cp;
            const float bx = bias[n], by = bias[n + 1];
            float2 lo = make_float2(acc[t][j][0] + bx, acc[t][j][1] + by);
            float2 hi = make_float2(acc[t][j][2] + bx, acc[t][j][3] + by);
            if (ADD_SKIP) {
                float2 s0 = *(const float2*)&skip[(size_t)r0 * kC + n];
                float2 s1 = *(const float2*)&skip[(size_t)(r0 + 8) * kC + n];
                lo.x += s0.x; lo.y += s0.y; hi.x += s1.x; hi.y += s1.y;
            }
            *(float2*)&out[(size_t)r0 * kC + n] = lo;
            *(float2*)&out[(size_t)(r0 + 8) * kC + n] = hi;
        }
    }
}

// ---------------------------------------------------------------------------
// Flash attention, fp32. One CTA = one (b, h, 64-query tile).
// Pitch 68 keeps every row base 16B-aligned -> LDS.128/STS.128 everywhere.
// ---------------------------------------------------------------------------
__global__ void __launch_bounds__(256)
attn_kernel()
{
    constexpr int SD = 68;
    extern __shared__ float sm[];
    float* Qs  = sm;                 // [d][q]
    float* Ksm = Qs  + 64 * SD;      // [d][k]
    float* Vsm = Ksm + 64 * SD;      // [k][d]
    float* Ps  = Vsm + 64 * SD;      // [q][k]

    const int tid = threadIdx.x;
    const int tx  = tid & 15;
    const int ty  = tid >> 4;
    const int b   = blockIdx.z;
    const int h   = blockIdx.y;
    const int q0  = blockIdx.x * 64;

    const float* Qg = g_q + (size_t)(b * kS + q0) * kC + h * kDH;
    const float* Kg = g_k + (size_t)(b * kS) * kC + h * kDH;
    const float* Vg = g_v + (size_t)(b * kS) * kC + h * kDH;

    // load Q tile transposed
#pragma unroll
    for (int r = 0; r < 4; r++) {
        int idx = tid + r * 256;          // 0..1023 float4s
        int row = idx >> 4;               // 0..63
        int c4  = (idx & 15) * 4;         // 0..60
        float4 qv = *(const float4*)(Qg + (size_t)row * kC + c4);
        Qs[(c4 + 0) * SD + row] = qv.x;
        Qs[(c4 + 1) * SD + row] = qv.y;
        Qs[(c4 + 2) * SD + row] = qv.z;
        Qs[(c4 + 3) * SD + row] = qv.w;
    }

    float m_i[4], l_i[4], accO[4][4];
#pragma unroll
    for (int i = 0; i < 4; i++) {
        m_i[i] = -INFINITY;
        l_i[i] = 0.f;
#pragma unroll
        for (int j = 0; j < 4; j++) accO[i][j] = 0.f;
    }
    const float cexp = 0.125f * 1.4426950408889634f;  // scale * log2(e)

    for (int kt = 0; kt < kS; kt += 64) {
        __syncthreads();   // prev iter done with Ks/Vs
#pragma unroll
        for (int r = 0; r < 4; r++) {
            int idx = tid + r * 256;
            int row = idx >> 4;
            int c4  = (idx & 15) * 4;
            float4 kv = *(const float4*)(Kg + (size_t)(kt + row) * kC + c4);
            Ksm[(c4 + 0) * SD + row] = kv.x;
            Ksm[(c4 + 1) * SD + row] = kv.y;
            Ksm[(c4 + 2) * SD + row] = kv.z;
            Ksm[(c4 + 3) * SD + row] = kv.w;
            float4 vv = *(const float4*)(Vg + (size_t)(kt + row) * kC + c4);
            *(float4*)&Vsm[row * SD + c4] = vv;
        }
        __syncthreads();

        // S = Q K^T
        float s[4][4];
#pragma unroll
        for (int i = 0; i < 4; i++)
#pragma unroll
            for (int j = 0; j < 4; j++) s[i][j] = 0.f;

#pragma unroll 8
        for (int d = 0; d < 64; d++) {
            float4 q4 = *(const float4*)&Qs[d * SD + ty * 4];
            float4 k4 = *(const float4*)&Ksm[d * SD + tx * 4];
            const float qf[4] = {q4.x, q4.y, q4.z, q4.w};
            const float kf[4] = {k4.x, k4.y, k4.z, k4.w};
#pragma unroll
            for (int i = 0; i < 4; i++)
#pragma unroll
                for (int j = 0; j < 4; j++)
                    s[i][j] = fmaf(qf[i], kf[j], s[i][j]);
        }

        // online softmax update per row
#pragma unroll
        for (int i = 0; i < 4; i++) {
            float rm = fmaxf(fmaxf(s[i][0], s[i][1]), fmaxf(s[i][2], s[i][3]));
            rm = fmaxf(rm, __shfl_xor_sync(0xffffffffu, rm, 1));
            rm = fmaxf(rm, __shfl_xor_sync(0xffffffffu, rm, 2));
            rm = fmaxf(rm, __shfl_xor_sync(0xffffffffu, rm, 4));
            rm = fmaxf(rm, __shfl_xor_sync(0xffffffffu, rm, 8));
            float m_new = fmaxf(m_i[i], rm);
            float alpha = exp2f((m_i[i] - m_new) * cexp);
            float rs = 0.f;
#pragma unroll
            for (int j = 0; j < 4; j++) {
                s[i][j] = exp2f((s[i][j] - m_new) * cexp);
                rs += s[i][j];
            }
            rs += __shfl_xor_sync(0xffffffffu, rs, 1);
            rs += __shfl_xor_sync(0xffffffffu, rs, 2);
            rs += __shfl_xor_sync(0xffffffffu, rs, 4);
            rs += __shfl_xor_sync(0xffffffffu, rs, 8);
            l_i[i] = l_i[i] * alpha + rs;
            m_i[i] = m_new;
#pragma unroll
            for (int j = 0; j < 4; j++) accO[i][j] *= alpha;
        }

        // P -> smem (vector stores)
#pragma unroll
        for (int i = 0; i < 4; i++) {
            float4 p4 = make_float4(s[i][0], s[i][1], s[i][2], s[i][3]);
            *(float4*)&Ps[(ty * 4 + i) * SD + tx * 4] = p4;
        }
        __syncthreads();

        // O += P V   (pf are intra-half-warp broadcasts; vf is LDS.128)
#pragma unroll 8
        for (int kk2 = 0; kk2 < 64; kk2++) {
            float pf[4];
#pragma unroll
            for (int i = 0; i < 4; i++) pf[i] = Ps[(ty * 4 + i) * SD + kk2];
            float4 v4 = *(const float4*)&Vsm[kk2 * SD + tx * 4];
            const float vf[4] = {v4.x, v4.y, v4.z, v4.w};
#pragma unroll
            for (int i = 0; i < 4; i++)
#pragma unroll
                for (int j = 0; j < 4; j++)
                    accO[i][j] = fmaf(pf[i], vf[j], accO[i][j]);
        }
    }

    // normalize + write ctx
    float* Og = g_ctx + (size_t)(b * kS + q0) * kC + h * kDH;
#pragma unroll
    for (int i = 0; i < 4; i++) {
        float inv = 1.f / l_i[i];
        int q = ty * 4 + i;
        float4 r = make_float4(accO[i][0] * inv, accO[i][1] * inv,
                               accO[i][2] * inv, accO[i][3] * inv);
        *(float4*)&Og[(size_t)q * kC + tx * 4] = r;
    }
}

// ---------------------------------------------------------------------------
// Launch
// ---------------------------------------------------------------------------
extern "C" void kernel_launch(void* const* d_in, const int* in_sizes, int n_in,
                              void* d_out, int out_size)
{
    (void)in_sizes; (void)n_in; (void)out_size;
    const float* x    = (const float*)d_in[0];
    const float* skip = (const float*)d_in[1];
    const float* Wq   = (const float*)d_in[2];
    const float* bq   = (const float*)d_in[3];
    const float* Wk   = (const float*)d_in[4];
    const float* bk   = (const float*)d_in[5];
    const float* Wv   = (const float*)d_in[6];
    const float* bv   = (const float*)d_in[7];
    const float* Wo   = (const float*)d_in[8];
    const float* bo   = (const float*)d_in[9];
    float* out = (float*)d_out;

    float *qb, *kb, *vb, *ctxb;
    cudaGetSymbolAddress((void**)&qb,   g_q);
    cudaGetSymbolAddress((void**)&kb,   g_k);
    cudaGetSymbolAddress((void**)&vb,   g_v);
    cudaGetSymbolAddress((void**)&ctxb, g_ctx);

    constexpr int kAttnSmem = 4 * 64 * 68 * 4;   // 69632 B
    cudaFuncSetAttribute(attn_kernel, cudaFuncAttributeMaxDynamicSharedMemorySize,
                         kAttnSmem);

    dim3 gemm_grid(kC / 128, kM / 128);   // (4, 64)
    gemm_tf32_kernel<false><<<gemm_grid, 256>>>(x, Wq, bq, nullptr, qb);
    gemm_tf32_kernel<false><<<gemm_grid, 256>>>(x, Wk, bk, nullptr, kb);
    gemm_tf32_kernel<false><<<gemm_grid, 256>>>(x, Wv, bv, nullptr, vb);

    attn_kernel<<<dim3(kS / 64, kH, kB), 256, kAttnSmem>>>();

    gemm_tf32_kernel<true><<<gemm_grid, 256>>>(ctxb, Wo, bo, skip, out);
}

// round 6
// speedup vs baseline: 5.0113x; 2.0877x over previous
#include <cuda_runtime.h>
#include <math.h>
#include <stdint.h>

// Problem constants: B=8, S=1024, C=512, H=8, DH=64
namespace {
constexpr int kB  = 8;
constexpr int kS  = 1024;
constexpr int kC  = 512;
constexpr int kH  = 8;
constexpr int kDH = 64;
constexpr int kM  = kB * kS;   // 8192 rows
}

// Scratch (allocation-free: device globals). 4 x 16 MB.
__device__ float g_q[kM * kC];
__device__ float g_k[kM * kC];
__device__ float g_v[kM * kC];     // holds Vt: [512][8192] = [h*64+d][b*1024+s]
__device__ float g_ctx[kM * kC];

// ===========================================================================
// Legacy tensor-core helpers (base sm_103 target; tcgen05 is ptxas-rejected)
// ===========================================================================
__device__ __forceinline__ uint32_t smem_u32(const void* p) {
    uint32_t a;
    asm("{ .reg .u64 t; cvta.to.shared.u64 t, %1; cvt.u32.u64 %0, t; }"
        : "=r"(a) : "l"(p));
    return a;
}

__device__ __forceinline__ uint32_t f2tf32(float f) {
    uint32_t u;
    asm("cvt.rna.tf32.f32 %0, %1;" : "=r"(u) : "f"(f));
    return u;
}

__device__ __forceinline__ void ldmatrix_x4(uint32_t& r0, uint32_t& r1,
                                            uint32_t& r2, uint32_t& r3,
                                            uint32_t addr) {
    asm volatile("ldmatrix.sync.aligned.m8n8.x4.shared.b16 {%0,%1,%2,%3}, [%4];"
                 : "=r"(r0), "=r"(r1), "=r"(r2), "=r"(r3) : "r"(addr));
}

// D(16x8) += A(16x8) * B(8x8), tf32 inputs, fp32 accumulate.
__device__ __forceinline__ void mma_tf32(float* c, uint32_t a0, uint32_t a1,
                                         uint32_t a2, uint32_t a3,
                                         uint32_t b0, uint32_t b1) {
    asm volatile(
        "mma.sync.aligned.m16n8k8.row.col.f32.tf32.tf32.f32 "
        "{%0,%1,%2,%3}, {%4,%5,%6,%7}, {%8,%9}, {%0,%1,%2,%3};"
        : "+f"(c[0]), "+f"(c[1]), "+f"(c[2]), "+f"(c[3])
        : "r"(a0), "r"(a1), "r"(a2), "r"(a3), "r"(b0), "r"(b1));
}

// ===========================================================================
// tf32 mma.sync GEMM: out[m,n] = sum_k X[m,k]*W[n,k] + bias + (skip)
// K = 512 fixed (row stride of X and W). Output row stride = N (param).
// BIAS_ROW: bias indexed by m (for the transposed-V GEMM), else by n.
// CTA 128x128, BK=16, 8 warps each 32(m) x 64(n). smem pitch 20 floats.
// ===========================================================================
namespace { constexpr int PK = 20; }

template <bool ADD_SKIP, bool BIAS_ROW>
__global__ void __launch_bounds__(256)
gemm_tf32_kernel(const float* __restrict__ X, const float* __restrict__ W,
                 const float* __restrict__ bias, const float* __restrict__ skip,
                 float* __restrict__ out, int N)
{
    __shared__ __align__(16) uint32_t sA[128 * PK];
    __shared__ __align__(16) uint32_t sB[128 * PK];

    const int tid = threadIdx.x;
    const int lid = tid & 31;
    const int wid = tid >> 5;
    const int m0  = blockIdx.y * 128;
    const int n0  = blockIdx.x * 128;
    const int wm  = (wid >> 1) * 32;   // warp m-offset within tile
    const int wn  = (wid & 1) * 64;    // warp n-offset within tile

    const int lrow = tid >> 2;         // 0..63
    const int lc4  = (tid & 3) * 4;    // 0,4,8,12

    const float* Ap = X + (size_t)(m0 + lrow) * kC + lc4;
    const float* Bp = W + (size_t)(n0 + lrow) * kC + lc4;

    const uint32_t sAu = smem_u32(sA);
    const uint32_t sBu = smem_u32(sB);
    uint32_t a_addr[2], b_addr[4];
#pragma unroll
    for (int t = 0; t < 2; t++)
        a_addr[t] = sAu + (((wm + 16 * t + (lid & 15)) * PK + ((lid >> 4) << 2)) << 2);
#pragma unroll
    for (int jj = 0; jj < 4; jj++)
        b_addr[jj] = sBu + (((wn + 16 * jj + ((lid >> 4) << 3) + (lid & 7)) * PK
                             + (((lid >> 3) & 1) << 2)) << 2);

    float acc[2][8][4];
#pragma unroll
    for (int t = 0; t < 2; t++)
#pragma unroll
        for (int j = 0; j < 8; j++)
#pragma unroll
            for (int c = 0; c < 4; c++) acc[t][j][c] = 0.f;

    // prefetch slab 0
    float4 pa0 = *(const float4*)Ap;
    float4 pa1 = *(const float4*)(Ap + (size_t)64 * kC);
    float4 pb0 = *(const float4*)Bp;
    float4 pb1 = *(const float4*)(Bp + (size_t)64 * kC);

#pragma unroll 1
    for (int s = 0; s < kC / 16; s++) {
        __syncthreads();
        {
            uint32_t* da = &sA[lrow * PK + lc4];
            da[0] = f2tf32(pa0.x); da[1] = f2tf32(pa0.y);
            da[2] = f2tf32(pa0.z); da[3] = f2tf32(pa0.w);
            uint32_t* da2 = da + 64 * PK;
            da2[0] = f2tf32(pa1.x); da2[1] = f2tf32(pa1.y);
            da2[2] = f2tf32(pa1.z); da2[3] = f2tf32(pa1.w);
            uint32_t* db = &sB[lrow * PK + lc4];
            db[0] = f2tf32(pb0.x); db[1] = f2tf32(pb0.y);
            db[2] = f2tf32(pb0.z); db[3] = f2tf32(pb0.w);
            uint32_t* db2 = db + 64 * PK;
            db2[0] = f2tf32(pb1.x); db2[1] = f2tf32(pb1.y);
            db2[2] = f2tf32(pb1.z); db2[3] = f2tf32(pb1.w);
        }
        __syncthreads();

        if (s + 1 < kC / 16) {
            Ap += 16; Bp += 16;
            pa0 = *(const float4*)Ap;
            pa1 = *(const float4*)(Ap + (size_t)64 * kC);
            pb0 = *(const float4*)Bp;
            pb1 = *(const float4*)(Bp + (size_t)64 * kC);
        }

#pragma unroll
        for (int ks = 0; ks < 2; ks++) {
            const uint32_t koff = ks * 32;
            uint32_t a[2][4];
#pragma unroll
            for (int t = 0; t < 2; t++)
                ldmatrix_x4(a[t][0], a[t][1], a[t][2], a[t][3], a_addr[t] + koff);
            uint32_t b[8][2];
#pragma unroll
            for (int jj = 0; jj < 4; jj++) {
                uint32_t r0, r1, r2, r3;
                ldmatrix_x4(r0, r1, r2, r3, b_addr[jj] + koff);
                b[2 * jj][0] = r0;  b[2 * jj][1] = r1;
                b[2 * jj + 1][0] = r2;  b[2 * jj + 1][1] = r3;
            }
#pragma unroll
            for (int t = 0; t < 2; t++)
#pragma unroll
                for (int j = 0; j < 8; j++)
                    mma_tf32(acc[t][j], a[t][0], a[t][1], a[t][2], a[t][3],
                             b[j][0], b[j][1]);
        }
    }

    const int g  = lid >> 2;
    const int cp = (lid & 3) * 2;
#pragma unroll
    for (int t = 0; t < 2; t++) {
        const int r0 = m0 + wm + 16 * t + g;
        float br0 = 0.f, br1 = 0.f;
        if (BIAS_ROW) { br0 = bias[r0]; br1 = bias[r0 + 8]; }
#pragma unroll
        for (int j = 0; j < 8; j++) {
            const int n = n0 + wn + 8 * j + cp;
            float bx, by, bx1, by1;
            if (BIAS_ROW) { bx = br0; by = br0; bx1 = br1; by1 = br1; }
            else { bx = bias[n]; by = bias[n + 1]; bx1 = bx; by1 = by; }
            float2 lo = make_float2(acc[t][j][0] + bx, acc[t][j][1] + by);
            float2 hi = make_float2(acc[t][j][2] + bx1, acc[t][j][3] + by1);
            if (ADD_SKIP) {
                float2 s0 = *(const float2*)&skip[(size_t)r0 * N + n];
                float2 s1 = *(const float2*)&skip[(size_t)(r0 + 8) * N + n];
                lo.x += s0.x; lo.y += s0.y; hi.x += s1.x; hi.y += s1.y;
            }
            *(float2*)&out[(size_t)r0 * N + n] = lo;
            *(float2*)&out[(size_t)(r0 + 8) * N + n] = hi;
        }
    }
}

// ===========================================================================
// Tensor-core flash attention (tf32 mma.sync).
// CTA = 128 queries x one (b,h); 8 warps x 16 query rows; key tiles of 64.
// smem: Qs[128][68] | Ks[64][68] | Vts[64][68] | Ps[128][68]  (tf32 words)
// Pitch 68: 16B-aligned rows, conflict-free ldmatrix (4r+4c distinct banks).
// V comes in pre-transposed (g_v = Vt[512][8192]) so its B-fragments load
// with natural contiguous float4s.
// ===========================================================================
namespace { constexpr int PQ = 68; constexpr int ATTN_SMEM = 384 * PQ * 4; }

__global__ void __launch_bounds__(256, 2)
attn_tc_kernel()
{
    extern __shared__ uint32_t smu[];
    uint32_t* Qs  = smu;               // [128][PQ]
    uint32_t* Ks  = Qs  + 128 * PQ;    // [64][PQ]
    uint32_t* Vts = Ks  + 64 * PQ;     // [64][PQ]
    uint32_t* Ps  = Vts + 64 * PQ;     // [128][PQ]

    const int tid = threadIdx.x;
    const int lid = tid & 31;
    const int wid = tid >> 5;
    const int b   = blockIdx.z;
    const int h   = blockIdx.y;
    const int q0  = blockIdx.x * 128;

    const float* Qg  = g_q + (size_t)(b * kS + q0) * kC + h * kDH;
    const float* Kg  = g_k + (size_t)(b * kS) * kC + h * kDH;
    const float* Vtg = g_v + (size_t)(h * kDH) * kM + (size_t)b * kS;

    // load Q tile (128 x 64), convert to tf32
#pragma unroll
    for (int t = 0; t < 8; t++) {
        int idx = tid + t * 256;          // 0..2047
        int row = idx >> 4;
        int c4  = (idx & 15) * 4;
        float4 q = *(const float4*)(Qg + (size_t)row * kC + c4);
        uint32_t* d = &Qs[row * PQ + c4];
        d[0] = f2tf32(q.x); d[1] = f2tf32(q.y);
        d[2] = f2tf32(q.z); d[3] = f2tf32(q.w);
    }

    // fragment addresses (slab-invariant)
    const uint32_t aq = smem_u32(Qs) +
        (((wid * 16 + (lid & 15)) * PQ + ((lid >> 4) << 2)) << 2);
    const uint32_t ap = smem_u32(Ps) +
        (((wid * 16 + (lid & 15)) * PQ + ((lid >> 4) << 2)) << 2);
    uint32_t bk[4], bv[4];
#pragma unroll
    for (int jj = 0; jj < 4; jj++) {
        uint32_t roff = ((16 * jj + ((lid >> 4) << 3) + (lid & 7)) * PQ
                         + (((lid >> 3) & 1) << 2)) << 2;
        bk[jj] = smem_u32(Ks)  + roff;
        bv[jj] = smem_u32(Vts) + roff;
    }

    float m_i[2] = {-INFINITY, -INFINITY};
    float l_i[2] = {0.f, 0.f};
    float accO[8][4];
#pragma unroll
    for (int j = 0; j < 8; j++)
#pragma unroll
        for (int c = 0; c < 4; c++) accO[j][c] = 0.f;
    const float cexp = 0.125f * 1.4426950408889634f;  // scale * log2(e)

    const int pr = wid * 16 + (lid >> 2);     // this thread's row (and +8)
    const int pc = (lid & 3) * 2;             // col pair base within 8-block

#pragma unroll 1
    for (int kt = 0; kt < kS; kt += 64) {
        __syncthreads();   // all warps done reading K/Vt of prev tile
        // load K tile [64 keys][64 d] and Vt tile [64 d][64 keys]
#pragma unroll
        for (int t = 0; t < 4; t++) {
            int idx = tid + t * 256;      // 0..1023
            int row = idx >> 4;
            int c4  = (idx & 15) * 4;
            float4 kv = *(const float4*)(Kg + (size_t)(kt + row) * kC + c4);
            uint32_t* dk = &Ks[row * PQ + c4];
            dk[0] = f2tf32(kv.x); dk[1] = f2tf32(kv.y);
            dk[2] = f2tf32(kv.z); dk[3] = f2tf32(kv.w);
            float4 vv = *(const float4*)(Vtg + (size_t)row * kM + kt + c4);
            uint32_t* dv = &Vts[row * PQ + c4];
            dv[0] = f2tf32(vv.x); dv[1] = f2tf32(vv.y);
            dv[2] = f2tf32(vv.z); dv[3] = f2tf32(vv.w);
        }
        __syncthreads();

        // S = Q K^T  -> s[8 key-blocks][4]
        float s[8][4];
#pragma unroll
        for (int j = 0; j < 8; j++)
#pragma unroll
            for (int c = 0; c < 4; c++) s[j][c] = 0.f;
#pragma unroll
        for (int ks = 0; ks < 8; ks++) {
            uint32_t a0, a1, a2, a3;
            ldmatrix_x4(a0, a1, a2, a3, aq + ks * 32);
            uint32_t bf[8][2];
#pragma unroll
            for (int jj = 0; jj < 4; jj++) {
                uint32_t r0, r1, r2, r3;
                ldmatrix_x4(r0, r1, r2, r3, bk[jj] + ks * 32);
                bf[2 * jj][0] = r0;  bf[2 * jj][1] = r1;
                bf[2 * jj + 1][0] = r2;  bf[2 * jj + 1][1] = r3;
            }
#pragma unroll
            for (int j = 0; j < 8; j++)
                mma_tf32(s[j], a0, a1, a2, a3, bf[j][0], bf[j][1]);
        }

        // online softmax per owned row (half 0: row pr; half 1: row pr+8)
#pragma unroll
        for (int hf = 0; hf < 2; hf++) {
            const int c0 = 2 * hf, c1 = 2 * hf + 1;
            float mx = fmaxf(s[0][c0], s[0][c1]);
#pragma unroll
            for (int j = 1; j < 8; j++)
                mx = fmaxf(mx, fmaxf(s[j][c0], s[j][c1]));
            mx = fmaxf(mx, __shfl_xor_sync(0xffffffffu, mx, 1));
            mx = fmaxf(mx, __shfl_xor_sync(0xffffffffu, mx, 2));
            float mnew = fmaxf(m_i[hf], mx);
            float alpha = exp2f((m_i[hf] - mnew) * cexp);
            float rs = 0.f;
#pragma unroll
            for (int j = 0; j < 8; j++) {
                s[j][c0] = exp2f((s[j][c0] - mnew) * cexp);
                s[j][c1] = exp2f((s[j][c1] - mnew) * cexp);
                rs += s[j][c0] + s[j][c1];
            }
            rs += __shfl_xor_sync(0xffffffffu, rs, 1);
            rs += __shfl_xor_sync(0xffffffffu, rs, 2);
            l_i[hf] = l_i[hf] * alpha + rs;
            m_i[hf] = mnew;
#pragma unroll
            for (int j = 0; j < 8; j++) {
                accO[j][c0] *= alpha;
                accO[j][c1] *= alpha;
            }
        }

        // P -> smem (tf32), warp-private rows
#pragma unroll
        for (int j = 0; j < 8; j++) {
            uint32_t* p0 = &Ps[pr * PQ + 8 * j + pc];
            p0[0] = f2tf32(s[j][0]); p0[1] = f2tf32(s[j][1]);
            uint32_t* p1 = &Ps[(pr + 8) * PQ + 8 * j + pc];
            p1[0] = f2tf32(s[j][2]); p1[1] = f2tf32(s[j][3]);
        }
        __syncwarp();

        // O += P * V   (accumulate over 64 keys)
#pragma unroll
        for (int ks = 0; ks < 8; ks++) {
            uint32_t a0, a1, a2, a3;
            ldmatrix_x4(a0, a1, a2, a3, ap + ks * 32);
            uint32_t bf[8][2];
#pragma unroll
            for (int jj = 0; jj < 4; jj++) {
                uint32_t r0, r1, r2, r3;
                ldmatrix_x4(r0, r1, r2, r3, bv[jj] + ks * 32);
                bf[2 * jj][0] = r0;  bf[2 * jj][1] = r1;
                bf[2 * jj + 1][0] = r2;  bf[2 * jj + 1][1] = r3;
            }
#pragma unroll
            for (int j = 0; j < 8; j++)
                mma_tf32(accO[j], a0, a1, a2, a3, bf[j][0], bf[j][1]);
        }
    }

    // normalize + write ctx [8192][512]
    {
        const float inv0 = 1.f / l_i[0];
        const float inv1 = 1.f / l_i[1];
        float* O0 = g_ctx + (size_t)(b * kS + q0 + pr) * kC + h * kDH;
        float* O1 = O0 + (size_t)8 * kC;
#pragma unroll
        for (int j = 0; j < 8; j++) {
            const int c = 8 * j + pc;
            *(float2*)&O0[c] = make_float2(accO[j][0] * inv0, accO[j][1] * inv0);
            *(float2*)&O1[c] = make_float2(accO[j][2] * inv1, accO[j][3] * inv1);
        }
    }
}

// ---------------------------------------------------------------------------
// Launch
// ---------------------------------------------------------------------------
extern "C" void kernel_launch(void* const* d_in, const int* in_sizes, int n_in,
                              void* d_out, int out_size)
{
    (void)in_sizes; (void)n_in; (void)out_size;
    const float* x    = (const float*)d_in[0];
    const float* skip = (const float*)d_in[1];
    const float* Wq   = (const float*)d_in[2];
    const float* bq   = (const float*)d_in[3];
    const float* Wk   = (const float*)d_in[4];
    const float* bk   = (const float*)d_in[5];
    const float* Wv   = (const float*)d_in[6];
    const float* bv   = (const float*)d_in[7];
    const float* Wo   = (const float*)d_in[8];
    const float* bo   = (const float*)d_in[9];
    float* out = (float*)d_out;

    float *qb, *kb, *vtb, *ctxb;
    cudaGetSymbolAddress((void**)&qb,   g_q);
    cudaGetSymbolAddress((void**)&kb,   g_k);
    cudaGetSymbolAddress((void**)&vtb,  g_v);
    cudaGetSymbolAddress((void**)&ctxb, g_ctx);

    cudaFuncSetAttribute(attn_tc_kernel,
                         cudaFuncAttributeMaxDynamicSharedMemorySize, ATTN_SMEM);

    dim3 gemm_grid(kC / 128, kM / 128);   // (4, 64)
    gemm_tf32_kernel<false, false><<<gemm_grid, 256>>>(x, Wq, bq, nullptr, qb, kC);
    gemm_tf32_kernel<false, false><<<gemm_grid, 256>>>(x, Wk, bk, nullptr, kb, kC);
    // V projection computed transposed: Vt[c][m] = Wv[c,:]·x[m,:] + bv[c]
    dim3 vt_grid(kM / 128, kC / 128);     // (64, 4) -> out [512][8192]
    gemm_tf32_kernel<false, true><<<vt_grid, 256>>>(Wv, x, bv, nullptr, vtb, kM);

    attn_tc_kernel<<<dim3(kS / 128, kH, kB), 256, ATTN_SMEM>>>();

    gemm_tf32_kernel<true, false><<<gemm_grid, 256>>>(ctxb, Wo, bo, skip, out, kC);
}

// round 7
// speedup vs baseline: 8.1925x; 1.6348x over previous
#include <cuda_runtime.h>
#include <cuda_fp16.h>
#include <math.h>
#include <stdint.h>

// Problem constants: B=8, S=1024, C=512, H=8, DH=64
namespace {
constexpr int kB  = 8;
constexpr int kS  = 1024;
constexpr int kC  = 512;
constexpr int kH  = 8;
constexpr int kDH = 64;
constexpr int kM  = kB * kS;   // 8192 rows
}

// Scratch (allocation-free: device globals). 4 x 16 MB.
__device__ float g_q[kM * kC];
__device__ float g_k[kM * kC];
__device__ float g_v[kM * kC];     // natural layout [m][c] (trans ldmatrix in attn)
__device__ float g_ctx[kM * kC];

// ===========================================================================
// Helpers (base sm_103 target; tcgen05 is ptxas-rejected on this harness)
// ===========================================================================
__device__ __forceinline__ uint32_t smem_u32(const void* p) {
    uint32_t a;
    asm("{ .reg .u64 t; cvta.to.shared.u64 t, %1; cvt.u32.u64 %0, t; }"
        : "=r"(a) : "l"(p));
    return a;
}

__device__ __forceinline__ uint32_t f2h2(float lo, float hi) {
    __half2 h = __float22half2_rn(make_float2(lo, hi));
    return *reinterpret_cast<uint32_t*>(&h);
}

__device__ __forceinline__ void ldmatrix_x4(uint32_t& r0, uint32_t& r1,
                                            uint32_t& r2, uint32_t& r3,
                                            uint32_t addr) {
    asm volatile("ldmatrix.sync.aligned.m8n8.x4.shared.b16 {%0,%1,%2,%3}, [%4];"
                 : "=r"(r0), "=r"(r1), "=r"(r2), "=r"(r3) : "r"(addr));
}

__device__ __forceinline__ void ldmatrix_x4_trans(uint32_t& r0, uint32_t& r1,
                                                  uint32_t& r2, uint32_t& r3,
                                                  uint32_t addr) {
    asm volatile("ldmatrix.sync.aligned.m8n8.x4.trans.shared.b16 {%0,%1,%2,%3}, [%4];"
                 : "=r"(r0), "=r"(r1), "=r"(r2), "=r"(r3) : "r"(addr));
}

// D(16x8) += A(16x16) * B(16x8), f16 inputs, fp32 accumulate.
__device__ __forceinline__ void mma_f16(float* c, uint32_t a0, uint32_t a1,
                                        uint32_t a2, uint32_t a3,
                                        uint32_t b0, uint32_t b1) {
    asm volatile(
        "mma.sync.aligned.m16n8k16.row.col.f32.f16.f16.f32 "
        "{%0,%1,%2,%3}, {%4,%5,%6,%7}, {%8,%9}, {%0,%1,%2,%3};"
        : "+f"(c[0]), "+f"(c[1]), "+f"(c[2]), "+f"(c[3])
        : "r"(a0), "r"(a1), "r"(a2), "r"(a3), "r"(b0), "r"(b1));
}

// ===========================================================================
// f16 mma.sync GEMM: out[m,n] = sum_k X[m,k]*W[n,k] + bias[n] (+skip[m,n])
// M=8192, N=512, K=512. CTA 128x128, BK=16, 8 warps each 32(m) x 64(n).
// blockIdx.z selects one of up to 3 (W, bias, out) triples (fused QKV).
// smem pitch 24 halves (48 B): rows 16B-aligned; 48r mod 128 distinct -> no
// ldmatrix conflicts.
// ===========================================================================
namespace { constexpr int PKH = 24; }

struct QKVArgs {
    const float *W0, *W1, *W2;
    const float *b0, *b1, *b2;
    float *o0, *o1, *o2;
};

template <bool ADD_SKIP>
__global__ void __launch_bounds__(256)
gemm_f16_kernel(const float* __restrict__ X, QKVArgs args,
                const float* __restrict__ skip)
{
    __shared__ __align__(16) __half sA[128 * PKH];
    __shared__ __align__(16) __half sB[128 * PKH];

    const int z = blockIdx.z;
    const float* W    = (z == 0) ? args.W0 : (z == 1) ? args.W1 : args.W2;
    const float* bias = (z == 0) ? args.b0 : (z == 1) ? args.b1 : args.b2;
    float* out        = (z == 0) ? args.o0 : (z == 1) ? args.o1 : args.o2;

    const int tid = threadIdx.x;
    const int lid = tid & 31;
    const int wid = tid >> 5;
    const int m0  = blockIdx.y * 128;
    const int n0  = blockIdx.x * 128;
    const int wm  = (wid >> 1) * 32;
    const int wn  = (wid & 1) * 64;

    const int lrow = tid >> 2;         // 0..63
    const int lc4  = (tid & 3) * 4;    // 0,4,8,12 (half offset within 16)

    const float* Ap = X + (size_t)(m0 + lrow) * kC + lc4;
    const float* Bp = W + (size_t)(n0 + lrow) * kC + lc4;

    const uint32_t sAu = smem_u32(sA);
    const uint32_t sBu = smem_u32(sB);
    uint32_t a_addr[2], b_addr[4];
#pragma unroll
    for (int t = 0; t < 2; t++)
        a_addr[t] = sAu + (wm + 16 * t + (lid & 15)) * (PKH * 2) + ((lid >> 4) << 4);
#pragma unroll
    for (int jj = 0; jj < 4; jj++)
        b_addr[jj] = sBu + (wn + 16 * jj + ((lid >> 4) << 3) + (lid & 7)) * (PKH * 2)
                   + (((lid >> 3) & 1) << 4);

    float acc[2][8][4];
#pragma unroll
    for (int t = 0; t < 2; t++)
#pragma unroll
        for (int j = 0; j < 8; j++)
#pragma unroll
            for (int c = 0; c < 4; c++) acc[t][j][c] = 0.f;

    // prefetch slab 0
    float4 pa0 = *(const float4*)Ap;
    float4 pa1 = *(const float4*)(Ap + (size_t)64 * kC);
    float4 pb0 = *(const float4*)Bp;
    float4 pb1 = *(const float4*)(Bp + (size_t)64 * kC);

#pragma unroll 1
    for (int s = 0; s < kC / 16; s++) {
        __syncthreads();
        {
            uint2 w;
            w.x = f2h2(pa0.x, pa0.y); w.y = f2h2(pa0.z, pa0.w);
            *(uint2*)&sA[lrow * PKH + lc4] = w;
            w.x = f2h2(pa1.x, pa1.y); w.y = f2h2(pa1.z, pa1.w);
            *(uint2*)&sA[(lrow + 64) * PKH + lc4] = w;
            w.x = f2h2(pb0.x, pb0.y); w.y = f2h2(pb0.z, pb0.w);
            *(uint2*)&sB[lrow * PKH + lc4] = w;
            w.x = f2h2(pb1.x, pb1.y); w.y = f2h2(pb1.z, pb1.w);
            *(uint2*)&sB[(lrow + 64) * PKH + lc4] = w;
        }
        __syncthreads();

        if (s + 1 < kC / 16) {
            Ap += 16; Bp += 16;
            pa0 = *(const float4*)Ap;
            pa1 = *(const float4*)(Ap + (size_t)64 * kC);
            pb0 = *(const float4*)Bp;
            pb1 = *(const float4*)(Bp + (size_t)64 * kC);
        }

        uint32_t a[2][4];
#pragma unroll
        for (int t = 0; t < 2; t++)
            ldmatrix_x4(a[t][0], a[t][1], a[t][2], a[t][3], a_addr[t]);
        uint32_t b[8][2];
#pragma unroll
        for (int jj = 0; jj < 4; jj++) {
            uint32_t r0, r1, r2, r3;
            ldmatrix_x4(r0, r1, r2, r3, b_addr[jj]);
            b[2 * jj][0] = r0;  b[2 * jj][1] = r1;
            b[2 * jj + 1][0] = r2;  b[2 * jj + 1][1] = r3;
        }
#pragma unroll
        for (int t = 0; t < 2; t++)
#pragma unroll
            for (int j = 0; j < 8; j++)
                mma_f16(acc[t][j], a[t][0], a[t][1], a[t][2], a[t][3],
                        b[j][0], b[j][1]);
    }

    const int g  = lid >> 2;
    const int cp = (lid & 3) * 2;
#pragma unroll
    for (int t = 0; t < 2; t++) {
        const int r0 = m0 + wm + 16 * t + g;
#pragma unroll
        for (int j = 0; j < 8; j++) {
            const int n = n0 + wn + 8 * j + cp;
            const float bx = bias[n], by = bias[n + 1];
            float2 lo = make_float2(acc[t][j][0] + bx, acc[t][j][1] + by);
            float2 hi = make_float2(acc[t][j][2] + bx, acc[t][j][3] + by);
            if (ADD_SKIP) {
                float2 s0 = *(const float2*)&skip[(size_t)r0 * kC + n];
                float2 s1 = *(const float2*)&skip[(size_t)(r0 + 8) * kC + n];
                lo.x += s0.x; lo.y += s0.y; hi.x += s1.x; hi.y += s1.y;
            }
            *(float2*)&out[(size_t)r0 * kC + n] = lo;
            *(float2*)&out[(size_t)(r0 + 8) * kC + n] = hi;
        }
    }
}

// ===========================================================================
// Tensor-core flash attention (f16 mma.sync, fp32 accumulate).
// CTA = 128 queries x one (b,h); 8 warps x 16 query rows; key tiles of 64.
// smem (halves, pitch 72 = 144 B rows, conflict-free ldmatrix inc. trans):
//   Qs[128][72] | Ks[64][72] | Vs[64][72] | Ps[128][72]  -> 55296 B dynamic
// V is natural [keys][d]; PV B-fragments via ldmatrix.x4.trans.
// ===========================================================================
namespace { constexpr int PQH = 72; constexpr int ATTN_SMEM = 384 * PQH * 2; }

__global__ void __launch_bounds__(256, 2)
attn_tc_kernel()
{
    extern __shared__ __half smh[];
    __half* Qs = smh;               // [128][PQH]
    __half* Ks = Qs + 128 * PQH;    // [64][PQH]
    __half* Vs = Ks + 64 * PQH;     // [64][PQH]
    __half* Ps = Vs + 64 * PQH;     // [128][PQH]

    const int tid = threadIdx.x;
    const int lid = tid & 31;
    const int wid = tid >> 5;
    const int b   = blockIdx.z;
    const int h   = blockIdx.y;
    const int q0  = blockIdx.x * 128;

    const float* Qg = g_q + (size_t)(b * kS + q0) * kC + h * kDH;
    const float* Kg = g_k + (size_t)(b * kS) * kC + h * kDH;
    const float* Vg = g_v + (size_t)(b * kS) * kC + h * kDH;

    // load Q tile (128 x 64) -> f16
#pragma unroll
    for (int t = 0; t < 8; t++) {
        int idx = tid + t * 256;
        int row = idx >> 4;
        int c4  = (idx & 15) * 4;
        float4 q = *(const float4*)(Qg + (size_t)row * kC + c4);
        uint2 w; w.x = f2h2(q.x, q.y); w.y = f2h2(q.z, q.w);
        *(uint2*)&Qs[row * PQH + c4] = w;
    }

    // fragment addresses (tile-invariant)
    const uint32_t aq = smem_u32(Qs)
        + (wid * 16 + (lid & 15)) * (PQH * 2) + ((lid >> 4) << 4);
    const uint32_t ap = smem_u32(Ps)
        + (wid * 16 + (lid & 15)) * (PQH * 2) + ((lid >> 4) << 4);
    uint32_t bk[4], bvb[4];
#pragma unroll
    for (int jj = 0; jj < 4; jj++) {
        bk[jj] = smem_u32(Ks)
            + (16 * jj + ((lid >> 4) << 3) + (lid & 7)) * (PQH * 2)
            + (((lid >> 3) & 1) << 4);
        // trans V: rows = keys, 16B column chunks select d-block
        bvb[jj] = smem_u32(Vs)
            + ((((lid >> 3) & 1) << 3) + (lid & 7)) * (PQH * 2)
            + (((lid >> 4) + 2 * jj) << 4);
    }

    float m_i[2] = {-INFINITY, -INFINITY};
    float l_i[2] = {0.f, 0.f};
    float accO[8][4];
#pragma unroll
    for (int j = 0; j < 8; j++)
#pragma unroll
        for (int c = 0; c < 4; c++) accO[j][c] = 0.f;
    const float cexp = 0.125f * 1.4426950408889634f;  // scale * log2(e)

    const int pr = wid * 16 + (lid >> 2);
    const int pc = (lid & 3) * 2;

#pragma unroll 1
    for (int kt = 0; kt < kS; kt += 64) {
        __syncthreads();
        // load K tile [64 keys][64 d] and V tile [64 keys][64 d]
#pragma unroll
        for (int t = 0; t < 4; t++) {
            int idx = tid + t * 256;
            int row = idx >> 4;
            int c4  = (idx & 15) * 4;
            float4 kv = *(const float4*)(Kg + (size_t)(kt + row) * kC + c4);
            uint2 w; w.x = f2h2(kv.x, kv.y); w.y = f2h2(kv.z, kv.w);
            *(uint2*)&Ks[row * PQH + c4] = w;
            float4 vv = *(const float4*)(Vg + (size_t)(kt + row) * kC + c4);
            uint2 w2; w2.x = f2h2(vv.x, vv.y); w2.y = f2h2(vv.z, vv.w);
            *(uint2*)&Vs[row * PQH + c4] = w2;
        }
        __syncthreads();

        // S = Q K^T   (4 k16 steps over d=64)
        float s[8][4];
#pragma unroll
        for (int j = 0; j < 8; j++)
#pragma unroll
            for (int c = 0; c < 4; c++) s[j][c] = 0.f;
#pragma unroll
        for (int ks = 0; ks < 4; ks++) {
            uint32_t a0, a1, a2, a3;
            ldmatrix_x4(a0, a1, a2, a3, aq + ks * 32);
            uint32_t bf[8][2];
#pragma unroll
            for (int jj = 0; jj < 4; jj++) {
                uint32_t r0, r1, r2, r3;
                ldmatrix_x4(r0, r1, r2, r3, bk[jj] + ks * 32);
                bf[2 * jj][0] = r0;  bf[2 * jj][1] = r1;
                bf[2 * jj + 1][0] = r2;  bf[2 * jj + 1][1] = r3;
            }
#pragma unroll
            for (int j = 0; j < 8; j++)
                mma_f16(s[j], a0, a1, a2, a3, bf[j][0], bf[j][1]);
        }

        // online softmax (half 0: row pr; half 1: row pr+8)
#pragma unroll
        for (int hf = 0; hf < 2; hf++) {
            const int c0 = 2 * hf, c1 = 2 * hf + 1;
            float mx = fmaxf(s[0][c0], s[0][c1]);
#pragma unroll
            for (int j = 1; j < 8; j++)
                mx = fmaxf(mx, fmaxf(s[j][c0], s[j][c1]));
            mx = fmaxf(mx, __shfl_xor_sync(0xffffffffu, mx, 1));
            mx = fmaxf(mx, __shfl_xor_sync(0xffffffffu, mx, 2));
            float mnew = fmaxf(m_i[hf], mx);
            float alpha = exp2f((m_i[hf] - mnew) * cexp);
            float rs = 0.f;
#pragma unroll
            for (int j = 0; j < 8; j++) {
                s[j][c0] = exp2f((s[j][c0] - mnew) * cexp);
                s[j][c1] = exp2f((s[j][c1] - mnew) * cexp);
                rs += s[j][c0] + s[j][c1];
            }
            rs += __shfl_xor_sync(0xffffffffu, rs, 1);
            rs += __shfl_xor_sync(0xffffffffu, rs, 2);
            l_i[hf] = l_i[hf] * alpha + rs;
            m_i[hf] = mnew;
#pragma unroll
            for (int j = 0; j < 8; j++) {
                accO[j][c0] *= alpha;
                accO[j][c1] *= alpha;
            }
        }

        // P -> smem as f16 (warp-private rows)
#pragma unroll
        for (int j = 0; j < 8; j++) {
            *(uint32_t*)&Ps[pr * PQH + 8 * j + pc]       = f2h2(s[j][0], s[j][1]);
            *(uint32_t*)&Ps[(pr + 8) * PQH + 8 * j + pc] = f2h2(s[j][2], s[j][3]);
        }
        __syncwarp();

        // O += P * V  (4 k16 steps over 64 keys; V via trans ldmatrix)
#pragma unroll
        for (int ks = 0; ks < 4; ks++) {
            uint32_t a0, a1, a2, a3;
            ldmatrix_x4(a0, a1, a2, a3, ap + ks * 32);
            uint32_t bf[8][2];
#pragma unroll
            for (int jj = 0; jj < 4; jj++) {
                uint32_t r0, r1, r2, r3;
                ldmatrix_x4_trans(r0, r1, r2, r3,
                                  bvb[jj] + ks * 16 * (PQH * 2));
                bf[2 * jj][0] = r0;  bf[2 * jj][1] = r1;
                bf[2 * jj + 1][0] = r2;  bf[2 * jj + 1][1] = r3;
            }
#pragma unroll
            for (int j = 0; j < 8; j++)
                mma_f16(accO[j], a0, a1, a2, a3, bf[j][0], bf[j][1]);
        }
    }

    // normalize + write ctx [8192][512]
    {
        const float inv0 = 1.f / l_i[0];
        const float inv1 = 1.f / l_i[1];
        float* O0 = g_ctx + (size_t)(b * kS + q0 + pr) * kC + h * kDH;
        float* O1 = O0 + (size_t)8 * kC;
#pragma unroll
        for (int j = 0; j < 8; j++) {
            const int c = 8 * j + pc;
            *(float2*)&O0[c] = make_float2(accO[j][0] * inv0, accO[j][1] * inv0);
            *(float2*)&O1[c] = make_float2(accO[j][2] * inv1, accO[j][3] * inv1);
        }
    }
}

// ---------------------------------------------------------------------------
// Launch
// ---------------------------------------------------------------------------
extern "C" void kernel_launch(void* const* d_in, const int* in_sizes, int n_in,
                              void* d_out, int out_size)
{
    (void)in_sizes; (void)n_in; (void)out_size;
    const float* x    = (const float*)d_in[0];
    const float* skip = (const float*)d_in[1];
    const float* Wq   = (const float*)d_in[2];
    const float* bq   = (const float*)d_in[3];
    const float* Wk   = (const float*)d_in[4];
    const float* bk   = (const float*)d_in[5];
    const float* Wv   = (const float*)d_in[6];
    const float* bv   = (const float*)d_in[7];
    const float* Wo   = (const float*)d_in[8];
    const float* bo   = (const float*)d_in[9];
    float* out = (float*)d_out;

    float *qb, *kb, *vb, *ctxb;
    cudaGetSymbolAddress((void**)&qb,   g_q);
    cudaGetSymbolAddress((void**)&kb,   g_k);
    cudaGetSymbolAddress((void**)&vb,   g_v);
    cudaGetSymbolAddress((void**)&ctxb, g_ctx);

    cudaFuncSetAttribute(attn_tc_kernel,
                         cudaFuncAttributeMaxDynamicSharedMemorySize, ATTN_SMEM);

    // Fused Q/K/V projections: one launch, z selects weight/bias/output.
    QKVArgs qkv = { Wq, Wk, Wv, bq, bk, bv, qb, kb, vb };
    gemm_f16_kernel<false><<<dim3(kC / 128, kM / 128, 3), 256>>>(x, qkv, nullptr);

    attn_tc_kernel<<<dim3(kS / 128, kH, kB), 256, ATTN_SMEM>>>();

    QKVArgs oargs = { Wo, Wo, Wo, bo, bo, bo, out, out, out };
    gemm_f16_kernel<true><<<dim3(kC / 128, kM / 128, 1), 256>>>(ctxb, oargs, skip);
}

// round 8
// speedup vs baseline: 9.5399x; 1.1645x over previous
#include <cuda_runtime.h>
#include <cuda_fp16.h>
#include <math.h>
#include <stdint.h>

// Problem constants: B=8, S=1024, C=512, H=8, DH=64
namespace {
constexpr int kB  = 8;
constexpr int kS  = 1024;
constexpr int kC  = 512;
constexpr int kH  = 8;
constexpr int kDH = 64;
constexpr int kM  = kB * kS;   // 8192 rows
}

// Scratch (allocation-free device globals), all fp16.
__device__ __half g_xh[kM * kC];        // x converted
__device__ __half g_wh[4 * kC * kC];    // Wq,Wk,Wv,Wo converted
__device__ __half g_q[kM * kC];
__device__ __half g_k[kM * kC];
__device__ __half g_v[kM * kC];
__device__ __half g_ctx[kM * kC];

// ===========================================================================
// Helpers (base sm_103 target; tcgen05 is ptxas-rejected on this harness)
// ===========================================================================
__device__ __forceinline__ uint32_t smem_u32(const void* p) {
    uint32_t a;
    asm("{ .reg .u64 t; cvta.to.shared.u64 t, %1; cvt.u32.u64 %0, t; }"
        : "=r"(a) : "l"(p));
    return a;
}

__device__ __forceinline__ uint32_t f2h2(float lo, float hi) {
    __half2 h = __float22half2_rn(make_float2(lo, hi));
    return *reinterpret_cast<uint32_t*>(&h);
}

__device__ __forceinline__ void ldmatrix_x4(uint32_t& r0, uint32_t& r1,
                                            uint32_t& r2, uint32_t& r3,
                                            uint32_t addr) {
    asm volatile("ldmatrix.sync.aligned.m8n8.x4.shared.b16 {%0,%1,%2,%3}, [%4];"
                 : "=r"(r0), "=r"(r1), "=r"(r2), "=r"(r3) : "r"(addr));
}

__device__ __forceinline__ void ldmatrix_x4_trans(uint32_t& r0, uint32_t& r1,
                                                  uint32_t& r2, uint32_t& r3,
                                                  uint32_t addr) {
    asm volatile("ldmatrix.sync.aligned.m8n8.x4.trans.shared.b16 {%0,%1,%2,%3}, [%4];"
                 : "=r"(r0), "=r"(r1), "=r"(r2), "=r"(r3) : "r"(addr));
}

// D(16x8) += A(16x16) * B(16x8), f16 inputs, fp32 accumulate.
__device__ __forceinline__ void mma_f16(float* c, uint32_t a0, uint32_t a1,
                                        uint32_t a2, uint32_t a3,
                                        uint32_t b0, uint32_t b1) {
    asm volatile(
        "mma.sync.aligned.m16n8k16.row.col.f32.f16.f16.f32 "
        "{%0,%1,%2,%3}, {%4,%5,%6,%7}, {%8,%9}, {%0,%1,%2,%3};"
        : "+f"(c[0]), "+f"(c[1]), "+f"(c[2]), "+f"(c[3])
        : "r"(a0), "r"(a1), "r"(a2), "r"(a3), "r"(b0), "r"(b1));
}

// ===========================================================================
// fp32 -> fp16 pre-convert: x (kM*kC) and 4 weight matrices (kC*kC each).
// ===========================================================================
struct CvtArgs { const float* src[5]; };

namespace {
constexpr int NX4 = kM * kC / 4;   // float4 count of x
constexpr int NW4 = kC * kC / 4;   // float4 count of one W
}

__global__ void __launch_bounds__(256)
convert_kernel(CvtArgs a)
{
    int i = blockIdx.x * 256 + threadIdx.x;   // float4 index
    const float* src;
    __half* dst;
    int off;
    if (i < NX4) {
        src = a.src[0]; dst = g_xh; off = i;
    } else {
        int r = (i - NX4) >> 16;              // / NW4 (65536)
        off   = (i - NX4) & (NW4 - 1);
        src = a.src[1 + r]; dst = g_wh + r * kC * kC;
    }
    float4 v = ((const float4*)src)[off];
    uint2 w;
    w.x = f2h2(v.x, v.y);
    w.y = f2h2(v.z, v.w);
    *(uint2*)&dst[off * 4] = w;
}

// ===========================================================================
// f16-input mma.sync GEMM core: acc[m,n] = sum_k X[m,k]*W[n,k]
// CTA 128x128, BK=32 (2 x k16 per slab, 16 slabs), 8 warps 32(m) x 64(n).
// smem pitch 40 halves (80 B): rows 16B-aligned, 20r mod 32 distinct ->
// conflict-free ldmatrix.
// ===========================================================================
namespace { constexpr int PKH = 40; }

struct GemmSmem { __half A[128 * PKH]; __half B[128 * PKH]; };

// Runs the mainloop; leaves results in acc[2][8][4].
__device__ __forceinline__ void gemm_mainloop(
    const __half* __restrict__ X, const __half* __restrict__ W,
    int m0, int n0, GemmSmem& sm, float acc[2][8][4])
{
    const int tid = threadIdx.x;
    const int lid = tid & 31;
    const int wid = tid >> 5;
    const int wm  = (wid >> 1) * 32;
    const int wn  = (wid & 1) * 64;

    // loader: 2 16B-chunks per matrix per thread per slab
    const int lrow0 = tid >> 2;            // 0..63
    const int lc    = (tid & 3) * 8;       // half offset of 16B chunk

    const uint32_t sAu = smem_u32(sm.A);
    const uint32_t sBu = smem_u32(sm.B);
    uint32_t a_addr[2], b_addr[4];
#pragma unroll
    for (int t = 0; t < 2; t++)
        a_addr[t] = sAu + (wm + 16 * t + (lid & 15)) * (PKH * 2) + ((lid >> 4) << 4);
#pragma unroll
    for (int jj = 0; jj < 4; jj++)
        b_addr[jj] = sBu + (wn + 16 * jj + ((lid >> 4) << 3) + (lid & 7)) * (PKH * 2)
                   + (((lid >> 3) & 1) << 4);

#pragma unroll
    for (int t = 0; t < 2; t++)
#pragma unroll
        for (int j = 0; j < 8; j++)
#pragma unroll
            for (int c = 0; c < 4; c++) acc[t][j][c] = 0.f;

    // prefetch slab 0
    uint4 ra0 = *(const uint4*)(X + (size_t)(m0 + lrow0) * kC + lc);
    uint4 ra1 = *(const uint4*)(X + (size_t)(m0 + 64 + lrow0) * kC + lc);
    uint4 rb0 = *(const uint4*)(W + (size_t)(n0 + lrow0) * kC + lc);
    uint4 rb1 = *(const uint4*)(W + (size_t)(n0 + 64 + lrow0) * kC + lc);

#pragma unroll 1
    for (int s = 0; s < kC / 32; s++) {
        __syncthreads();
        *(uint4*)&sm.A[lrow0 * PKH + lc]        = ra0;
        *(uint4*)&sm.A[(lrow0 + 64) * PKH + lc] = ra1;
        *(uint4*)&sm.B[lrow0 * PKH + lc]        = rb0;
        *(uint4*)&sm.B[(lrow0 + 64) * PKH + lc] = rb1;
        __syncthreads();

        if (s + 1 < kC / 32) {
            const int k0 = (s + 1) * 32;
            ra0 = *(const uint4*)(X + (size_t)(m0 + lrow0) * kC + k0 + lc);
            ra1 = *(const uint4*)(X + (size_t)(m0 + 64 + lrow0) * kC + k0 + lc);
            rb0 = *(const uint4*)(W + (size_t)(n0 + lrow0) * kC + k0 + lc);
            rb1 = *(const uint4*)(W + (size_t)(n0 + 64 + lrow0) * kC + k0 + lc);
        }

#pragma unroll
        for (int ks = 0; ks < 2; ks++) {
            const uint32_t ko = ks * 32;   // 16 halves = 32 B
            uint32_t a[2][4];
#pragma unroll
            for (int t = 0; t < 2; t++)
                ldmatrix_x4(a[t][0], a[t][1], a[t][2], a[t][3], a_addr[t] + ko);
            uint32_t b[8][2];
#pragma unroll
            for (int jj = 0; jj < 4; jj++) {
                uint32_t r0, r1, r2, r3;
                ldmatrix_x4(r0, r1, r2, r3, b_addr[jj] + ko);
                b[2 * jj][0] = r0;  b[2 * jj][1] = r1;
                b[2 * jj + 1][0] = r2;  b[2 * jj + 1][1] = r3;
            }
#pragma unroll
            for (int t = 0; t < 2; t++)
#pragma unroll
                for (int j = 0; j < 8; j++)
                    mma_f16(acc[t][j], a[t][0], a[t][1], a[t][2], a[t][3],
                            b[j][0], b[j][1]);
        }
    }
}

// QKV fused GEMM: z selects (W, bias, half-out). X = g_xh.
struct QKVArgs { const float *b0, *b1, *b2; __half *o0, *o1, *o2; };

__global__ void __launch_bounds__(256)
gemm_qkv_kernel(QKVArgs args)
{
    __shared__ GemmSmem sm;
    const int z = blockIdx.z;
    const float* bias = (z == 0) ? args.b0 : (z == 1) ? args.b1 : args.b2;
    __half* out       = (z == 0) ? args.o0 : (z == 1) ? args.o1 : args.o2;
    const int m0 = blockIdx.y * 128;
    const int n0 = blockIdx.x * 128;

    float acc[2][8][4];
    gemm_mainloop(g_xh, g_wh + (size_t)z * kC * kC, m0, n0, sm, acc);

    const int lid = threadIdx.x & 31;
    const int wid = threadIdx.x >> 5;
    const int wm  = (wid >> 1) * 32;
    const int wn  = (wid & 1) * 64;
    const int g   = lid >> 2;
    const int cp  = (lid & 3) * 2;
#pragma unroll
    for (int t = 0; t < 2; t++) {
        const int r0 = m0 + wm + 16 * t + g;
#pragma unroll
        for (int j = 0; j < 8; j++) {
            const int n = n0 + wn + 8 * j + cp;
            const float bx = bias[n], by = bias[n + 1];
            *(uint32_t*)&out[(size_t)r0 * kC + n] =
                f2h2(acc[t][j][0] + bx, acc[t][j][1] + by);
            *(uint32_t*)&out[(size_t)(r0 + 8) * kC + n] =
                f2h2(acc[t][j][2] + bx, acc[t][j][3] + by);
        }
    }
}

// Output GEMM: X = g_ctx (half), W = Wo (converted), out fp32 + bias + skip.
__global__ void __launch_bounds__(256)
gemm_o_kernel(const float* __restrict__ bias, const float* __restrict__ skip,
              float* __restrict__ out)
{
    __shared__ GemmSmem sm;
    const int m0 = blockIdx.y * 128;
    const int n0 = blockIdx.x * 128;

    float acc[2][8][4];
    gemm_mainloop(g_ctx, g_wh + (size_t)3 * kC * kC, m0, n0, sm, acc);

    const int lid = threadIdx.x & 31;
    const int wid = threadIdx.x >> 5;
    const int wm  = (wid >> 1) * 32;
    const int wn  = (wid & 1) * 64;
    const int g   = lid >> 2;
    const int cp  = (lid & 3) * 2;
#pragma unroll
    for (int t = 0; t < 2; t++) {
        const int r0 = m0 + wm + 16 * t + g;
#pragma unroll
        for (int j = 0; j < 8; j++) {
            const int n = n0 + wn + 8 * j + cp;
            const float bx = bias[n], by = bias[n + 1];
            float2 s0 = *(const float2*)&skip[(size_t)r0 * kC + n];
            float2 s1 = *(const float2*)&skip[(size_t)(r0 + 8) * kC + n];
            *(float2*)&out[(size_t)r0 * kC + n] =
                make_float2(acc[t][j][0] + bx + s0.x, acc[t][j][1] + by + s0.y);
            *(float2*)&out[(size_t)(r0 + 8) * kC + n] =
                make_float2(acc[t][j][2] + bx + s1.x, acc[t][j][3] + by + s1.y);
        }
    }
}

// ===========================================================================
// Tensor-core flash attention (f16 mma.sync, fp32 accumulate).
// CTA = 128 queries x one (b,h); 8 warps x 16 query rows; key tiles of 64.
// Q fragments hoisted to registers (staged once through smem).
// P never hits smem: S C-fragments repack directly into PV A-fragments.
// smem: Ks[64][72] | Vs[64][72] halves = 18432 B (static).
// ===========================================================================
namespace { constexpr int PQH = 72; }

__global__ void __launch_bounds__(256, 2)
attn_tc_kernel()
{
    __shared__ __half sm[128 * PQH];
    __half* Ks = sm;               // [64][PQH]
    __half* Vs = sm + 64 * PQH;    // [64][PQH]

    const int tid = threadIdx.x;
    const int lid = tid & 31;
    const int wid = tid >> 5;
    const int b   = blockIdx.z;
    const int h   = blockIdx.y;
    const int q0  = blockIdx.x * 128;

    const __half* Qg = g_q + (size_t)(b * kS + q0) * kC + h * kDH;
    const __half* Kg = g_k + (size_t)(b * kS) * kC + h * kDH;
    const __half* Vg = g_v + (size_t)(b * kS) * kC + h * kDH;

    // --- Stage Q through smem once; extract loop-invariant A fragments ---
#pragma unroll
    for (int t = 0; t < 4; t++) {
        int idx = tid + t * 256;          // 0..1023 16B-chunks
        int row = idx >> 3;               // 0..127
        int c8  = (idx & 7) * 8;
        *(uint4*)&sm[row * PQH + c8] = *(const uint4*)(Qg + (size_t)row * kC + c8);
    }
    __syncthreads();
    uint32_t qf[4][4];
    {
        const uint32_t aq = smem_u32(sm)
            + (wid * 16 + (lid & 15)) * (PQH * 2) + ((lid >> 4) << 4);
#pragma unroll
        for (int ks = 0; ks < 4; ks++)
            ldmatrix_x4(qf[ks][0], qf[ks][1], qf[ks][2], qf[ks][3], aq + ks * 32);
    }
    __syncthreads();   // done with Q staging; smem now K/V

    // fragment addresses (tile-invariant)
    uint32_t bk[4], bvb[4];
#pragma unroll
    for (int jj = 0; jj < 4; jj++) {
        bk[jj] = smem_u32(Ks)
            + (16 * jj + ((lid >> 4) << 3) + (lid & 7)) * (PQH * 2)
            + (((lid >> 3) & 1) << 4);
        bvb[jj] = smem_u32(Vs)
            + ((((lid >> 3) & 1) << 3) + (lid & 7)) * (PQH * 2)
            + (((lid >> 4) + 2 * jj) << 4);
    }

    float m_i[2] = {-INFINITY, -INFINITY};
    float l_i[2] = {0.f, 0.f};
    float accO[8][4];
#pragma unroll
    for (int j = 0; j < 8; j++)
#pragma unroll
        for (int c = 0; c < 4; c++) accO[j][c] = 0.f;
    const float cexp = 0.125f * 1.4426950408889634f;  // scale * log2(e)

    const int pr = wid * 16 + (lid >> 2);
    const int pc = (lid & 3) * 2;

    // prefetch K/V tile 0
    uint4 pk[2], pv[2];
#pragma unroll
    for (int t = 0; t < 2; t++) {
        int idx = tid + t * 256;
        int row = idx >> 3;
        int c8  = (idx & 7) * 8;
        pk[t] = *(const uint4*)(Kg + (size_t)row * kC + c8);
        pv[t] = *(const uint4*)(Vg + (size_t)row * kC + c8);
    }

#pragma unroll 1
    for (int kt = 0; kt < kS; kt += 64) {
        // store staged tile (smem free: prev readers done at loop-end sync)
#pragma unroll
        for (int t = 0; t < 2; t++) {
            int idx = tid + t * 256;
            int row = idx >> 3;
            int c8  = (idx & 7) * 8;
            *(uint4*)&Ks[row * PQH + c8] = pk[t];
            *(uint4*)&Vs[row * PQH + c8] = pv[t];
        }
        __syncthreads();

        if (kt + 64 < kS) {
#pragma unroll
            for (int t = 0; t < 2; t++) {
                int idx = tid + t * 256;
                int row = idx >> 3;
                int c8  = (idx & 7) * 8;
                pk[t] = *(const uint4*)(Kg + (size_t)(kt + 64 + row) * kC + c8);
                pv[t] = *(const uint4*)(Vg + (size_t)(kt + 64 + row) * kC + c8);
            }
        }

        // S = Q K^T   (4 k16 steps over d=64)
        float s[8][4];
#pragma unroll
        for (int j = 0; j < 8; j++)
#pragma unroll
            for (int c = 0; c < 4; c++) s[j][c] = 0.f;
#pragma unroll
        for (int ks = 0; ks < 4; ks++) {
            uint32_t bf[8][2];
#pragma unroll
            for (int jj = 0; jj < 4; jj++) {
                uint32_t r0, r1, r2, r3;
                ldmatrix_x4(r0, r1, r2, r3, bk[jj] + ks * 32);
                bf[2 * jj][0] = r0;  bf[2 * jj][1] = r1;
                bf[2 * jj + 1][0] = r2;  bf[2 * jj + 1][1] = r3;
            }
#pragma unroll
            for (int j = 0; j < 8; j++)
                mma_f16(s[j], qf[ks][0], qf[ks][1], qf[ks][2], qf[ks][3],
                        bf[j][0], bf[j][1]);
        }

        // online softmax (half 0: row pr; half 1: row pr+8)
#pragma unroll
        for (int hf = 0; hf < 2; hf++) {
            const int c0 = 2 * hf, c1 = 2 * hf + 1;
            float mx = fmaxf(s[0][c0], s[0][c1]);
#pragma unroll
            for (int j = 1; j < 8; j++)
                mx = fmaxf(mx, fmaxf(s[j][c0], s[j][c1]));
            mx = fmaxf(mx, __shfl_xor_sync(0xffffffffu, mx, 1));
            mx = fmaxf(mx, __shfl_xor_sync(0xffffffffu, mx, 2));
            float mnew = fmaxf(m_i[hf], mx);
            float alpha = exp2f((m_i[hf] - mnew) * cexp);
            float rs = 0.f;
#pragma unroll
            for (int j = 0; j < 8; j++) {
                s[j][c0] = exp2f((s[j][c0] - mnew) * cexp);
                s[j][c1] = exp2f((s[j][c1] - mnew) * cexp);
                rs += s[j][c0] + s[j][c1];
            }
            rs += __shfl_xor_sync(0xffffffffu, rs, 1);
            rs += __shfl_xor_sync(0xffffffffu, rs, 2);
            l_i[hf] = l_i[hf] * alpha + rs;
            m_i[hf] = mnew;
#pragma unroll
            for (int j = 0; j < 8; j++) {
                accO[j][c0] *= alpha;
                accO[j][c1] *= alpha;
            }
        }

        // O += P * V : P's A-fragments come straight from S's C-fragments.
        // A m16n8k16 layout: a0=(r, k 2c..), a1=(r+8, k), a2=(r, k+8), a3=(r+8, k+8)
        // C m16n8 layout:    c0,c1=(r, 2c,2c+1), c2,c3=(r+8, 2c,2c+1)
#pragma unroll
        for (int ks = 0; ks < 4; ks++) {
            const uint32_t a0 = f2h2(s[2 * ks][0],     s[2 * ks][1]);
            const uint32_t a1 = f2h2(s[2 * ks][2],     s[2 * ks][3]);
            const uint32_t a2 = f2h2(s[2 * ks + 1][0], s[2 * ks + 1][1]);
            const uint32_t a3 = f2h2(s[2 * ks + 1][2], s[2 * ks + 1][3]);
            uint32_t bf[8][2];
#pragma unroll
            for (int jj = 0; jj < 4; jj++) {
                uint32_t r0, r1, r2, r3;
                ldmatrix_x4_trans(r0, r1, r2, r3,
                                  bvb[jj] + ks * 16 * (PQH * 2));
                bf[2 * jj][0] = r0;  bf[2 * jj][1] = r1;
                bf[2 * jj + 1][0] = r2;  bf[2 * jj + 1][1] = r3;
            }
#pragma unroll
            for (int j = 0; j < 8; j++)
                mma_f16(accO[j], a0, a1, a2, a3, bf[j][0], bf[j][1]);
        }
        __syncthreads();   // all warps done reading K/V before next store
    }

    // normalize + write ctx (fp16)
    {
        const float inv0 = 1.f / l_i[0];
        const float inv1 = 1.f / l_i[1];
        __half* O0 = g_ctx + (size_t)(b * kS + q0 + pr) * kC + h * kDH;
        __half* O1 = O0 + (size_t)8 * kC;
#pragma unroll
        for (int j = 0; j < 8; j++) {
            const int c = 8 * j + pc;
            *(uint32_t*)&O0[c] = f2h2(accO[j][0] * inv0, accO[j][1] * inv0);
            *(uint32_t*)&O1[c] = f2h2(accO[j][2] * inv1, accO[j][3] * inv1);
        }
    }
}

// ---------------------------------------------------------------------------
// Launch
// ---------------------------------------------------------------------------
extern "C" void kernel_launch(void* const* d_in, const int* in_sizes, int n_in,
                              void* d_out, int out_size)
{
    (void)in_sizes; (void)n_in; (void)out_size;
    const float* x    = (const float*)d_in[0];
    const float* skip = (const float*)d_in[1];
    const float* Wq   = (const float*)d_in[2];
    const float* bq   = (const float*)d_in[3];
    const float* Wk   = (const float*)d_in[4];
    const float* bk   = (const float*)d_in[5];
    const float* Wv   = (const float*)d_in[6];
    const float* bv   = (const float*)d_in[7];
    const float* Wo   = (const float*)d_in[8];
    const float* bo   = (const float*)d_in[9];
    float* out = (float*)d_out;

    __half *qb, *kb, *vb;
    cudaGetSymbolAddress((void**)&qb, g_q);
    cudaGetSymbolAddress((void**)&kb, g_k);
    cudaGetSymbolAddress((void**)&vb, g_v);

    // 1) convert x + weights to fp16
    CvtArgs ca; ca.src[0] = x; ca.src[1] = Wq; ca.src[2] = Wk;
    ca.src[3] = Wv; ca.src[4] = Wo;
    convert_kernel<<<(NX4 + 4 * NW4) / 256, 256>>>(ca);

    // 2) fused QKV projections
    QKVArgs qkv = { bq, bk, bv, qb, kb, vb };
    gemm_qkv_kernel<<<dim3(kC / 128, kM / 128, 3), 256>>>(qkv);

    // 3) attention
    attn_tc_kernel<<<dim3(kS / 128, kH, kB), 256>>>();

    // 4) output projection + bias + skip
    gemm_o_kernel<<<dim3(kC / 128, kM / 128, 1), 256>>>(bo, skip, out);
}

// round 9
// speedup vs baseline: 9.8336x; 1.0308x over previous
#include <cuda_runtime.h>
#include <cuda_fp16.h>
#include <math.h>
#include <stdint.h>

// Problem constants: B=8, S=1024, C=512, H=8, DH=64
namespace {
constexpr int kB  = 8;
constexpr int kS  = 1024;
constexpr int kC  = 512;
constexpr int kH  = 8;
constexpr int kDH = 64;
constexpr int kM  = kB * kS;   // 8192 rows
}

// Scratch (allocation-free device globals), all fp16.
__device__ __half g_xh[kM * kC];        // x converted
__device__ __half g_wh[4 * kC * kC];    // Wq,Wk,Wv,Wo converted
__device__ __half g_q[kM * kC];
__device__ __half g_k[kM * kC];
__device__ __half g_v[kM * kC];
__device__ __half g_ctx[kM * kC];

// ===========================================================================
// Helpers (base sm_103 target; tcgen05 is ptxas-rejected on this harness)
// ===========================================================================
__device__ __forceinline__ uint32_t smem_u32(const void* p) {
    uint32_t a;
    asm("{ .reg .u64 t; cvta.to.shared.u64 t, %1; cvt.u32.u64 %0, t; }"
        : "=r"(a) : "l"(p));
    return a;
}

__device__ __forceinline__ uint32_t f2h2(float lo, float hi) {
    __half2 h = __float22half2_rn(make_float2(lo, hi));
    return *reinterpret_cast<uint32_t*>(&h);
}

__device__ __forceinline__ void cp_async16(uint32_t dst, const void* src) {
    asm volatile("cp.async.cg.shared.global [%0], [%1], 16;"
                 :: "r"(dst), "l"(src));
}
#define CP_COMMIT() asm volatile("cp.async.commit_group;" ::: "memory")
#define CP_WAIT0()  asm volatile("cp.async.wait_group 0;" ::: "memory")

__device__ __forceinline__ void ldmatrix_x4(uint32_t& r0, uint32_t& r1,
                                            uint32_t& r2, uint32_t& r3,
                                            uint32_t addr) {
    asm volatile("ldmatrix.sync.aligned.m8n8.x4.shared.b16 {%0,%1,%2,%3}, [%4];"
                 : "=r"(r0), "=r"(r1), "=r"(r2), "=r"(r3) : "r"(addr));
}

__device__ __forceinline__ void ldmatrix_x4_trans(uint32_t& r0, uint32_t& r1,
                                                  uint32_t& r2, uint32_t& r3,
                                                  uint32_t addr) {
    asm volatile("ldmatrix.sync.aligned.m8n8.x4.trans.shared.b16 {%0,%1,%2,%3}, [%4];"
                 : "=r"(r0), "=r"(r1), "=r"(r2), "=r"(r3) : "r"(addr));
}

// D(16x8) += A(16x16) * B(16x8), f16 inputs, fp32 accumulate.
__device__ __forceinline__ void mma_f16(float* c, uint32_t a0, uint32_t a1,
                                        uint32_t a2, uint32_t a3,
                                        uint32_t b0, uint32_t b1) {
    asm volatile(
        "mma.sync.aligned.m16n8k16.row.col.f32.f16.f16.f32 "
        "{%0,%1,%2,%3}, {%4,%5,%6,%7}, {%8,%9}, {%0,%1,%2,%3};"
        : "+f"(c[0]), "+f"(c[1]), "+f"(c[2]), "+f"(c[3])
        : "r"(a0), "r"(a1), "r"(a2), "r"(a3), "r"(b0), "r"(b1));
}

// ===========================================================================
// fp32 -> fp16 pre-convert: x (kM*kC) and 4 weight matrices (kC*kC each).
// ===========================================================================
struct CvtArgs { const float* src[5]; };

namespace {
constexpr int NX4 = kM * kC / 4;   // float4 count of x
constexpr int NW4 = kC * kC / 4;   // float4 count of one W
}

__global__ void __launch_bounds__(256)
convert_kernel(CvtArgs a)
{
    int i = blockIdx.x * 256 + threadIdx.x;   // float4 index
    const float* src;
    __half* dst;
    int off;
    if (i < NX4) {
        src = a.src[0]; dst = g_xh; off = i;
    } else {
        int r = (i - NX4) >> 16;              // / NW4 (65536)
        off   = (i - NX4) & (NW4 - 1);
        src = a.src[1 + r]; dst = g_wh + r * kC * kC;
    }
    float4 v = ((const float4*)src)[off];
    uint2 w;
    w.x = f2h2(v.x, v.y);
    w.y = f2h2(v.z, v.w);
    *(uint2*)&dst[off * 4] = w;
}

// ===========================================================================
// f16-input mma.sync GEMM core: acc[m,n] = sum_k X[m,k]*W[n,k]
// CTA 128x128, BK=32 (2 x k16 per slab, 16 slabs), 8 warps 32(m) x 64(n).
// 2-stage cp.async pipeline: one __syncthreads per slab, loads overlapped
// with MMA. smem pitch 40 halves (80 B): conflict-free ldmatrix.
// ===========================================================================
namespace {
constexpr int PKH = 40;
constexpr int GEMM_TILE_B = 128 * PKH * 2;   // 10240 B per matrix per stage
}

struct GemmSmem { __half A[2][128 * PKH]; __half B[2][128 * PKH]; };  // 40 KB

// Runs the mainloop; leaves results in acc[2][8][4].
__device__ __forceinline__ void gemm_mainloop(
    const __half* __restrict__ X, const __half* __restrict__ W,
    int m0, int n0, GemmSmem& sm, float acc[2][8][4])
{
    const int tid = threadIdx.x;
    const int lid = tid & 31;
    const int wid = tid >> 5;
    const int wm  = (wid >> 1) * 32;
    const int wn  = (wid & 1) * 64;

    // loader: 2 16B-chunks per matrix per thread per slab
    const int lrow0 = tid >> 2;            // 0..63
    const int lc    = (tid & 3) * 8;       // half offset of 16B chunk

    const uint32_t sAu = smem_u32(sm.A[0]);
    const uint32_t sBu = smem_u32(sm.B[0]);

    // per-stage cp.async destinations (byte addresses, stage 0)
    const uint32_t dA0 = sAu + (lrow0 * PKH + lc) * 2;
    const uint32_t dA1 = dA0 + 64 * PKH * 2;
    const uint32_t dB0 = sBu + (lrow0 * PKH + lc) * 2;
    const uint32_t dB1 = dB0 + 64 * PKH * 2;

    const __half* gA0 = X + (size_t)(m0 + lrow0) * kC + lc;
    const __half* gA1 = X + (size_t)(m0 + 64 + lrow0) * kC + lc;
    const __half* gB0 = W + (size_t)(n0 + lrow0) * kC + lc;
    const __half* gB1 = W + (size_t)(n0 + 64 + lrow0) * kC + lc;

    // ldmatrix fragment addresses (stage 0)
    uint32_t a_addr[2], b_addr[4];
#pragma unroll
    for (int t = 0; t < 2; t++)
        a_addr[t] = sAu + (wm + 16 * t + (lid & 15)) * (PKH * 2) + ((lid >> 4) << 4);
#pragma unroll
    for (int jj = 0; jj < 4; jj++)
        b_addr[jj] = sBu + (wn + 16 * jj + ((lid >> 4) << 3) + (lid & 7)) * (PKH * 2)
                   + (((lid >> 3) & 1) << 4);

#pragma unroll
    for (int t = 0; t < 2; t++)
#pragma unroll
        for (int j = 0; j < 8; j++)
#pragma unroll
            for (int c = 0; c < 4; c++) acc[t][j][c] = 0.f;

    // prologue: issue slab 0 into stage 0
    cp_async16(dA0, gA0);
    cp_async16(dA1, gA1);
    cp_async16(dB0, gB0);
    cp_async16(dB1, gB1);
    CP_COMMIT();

#pragma unroll 1
    for (int s = 0; s < kC / 32; s++) {
        CP_WAIT0();
        __syncthreads();
        const uint32_t boff = (uint32_t)(s & 1) * GEMM_TILE_B;

        if (s + 1 < kC / 32) {
            const uint32_t noff = (uint32_t)((s + 1) & 1) * GEMM_TILE_B;
            const int k0 = (s + 1) * 32;
            cp_async16(dA0 + noff, gA0 + k0);
            cp_async16(dA1 + noff, gA1 + k0);
            cp_async16(dB0 + noff, gB0 + k0);
            cp_async16(dB1 + noff, gB1 + k0);
            CP_COMMIT();
        }

#pragma unroll
        for (int ks = 0; ks < 2; ks++) {
            const uint32_t ko = boff + ks * 32;   // 16 halves = 32 B
            uint32_t a[2][4];
#pragma unroll
            for (int t = 0; t < 2; t++)
                ldmatrix_x4(a[t][0], a[t][1], a[t][2], a[t][3], a_addr[t] + ko);
            uint32_t b[8][2];
#pragma unroll
            for (int jj = 0; jj < 4; jj++) {
                uint32_t r0, r1, r2, r3;
                ldmatrix_x4(r0, r1, r2, r3, b_addr[jj] + ko);
                b[2 * jj][0] = r0;  b[2 * jj][1] = r1;
                b[2 * jj + 1][0] = r2;  b[2 * jj + 1][1] = r3;
            }
#pragma unroll
            for (int t = 0; t < 2; t++)
#pragma unroll
                for (int j = 0; j < 8; j++)
                    mma_f16(acc[t][j], a[t][0], a[t][1], a[t][2], a[t][3],
                            b[j][0], b[j][1]);
        }
    }
}

// QKV fused GEMM: z selects (W, bias, half-out). X = g_xh.
struct QKVArgs { const float *b0, *b1, *b2; __half *o0, *o1, *o2; };

__global__ void __launch_bounds__(256)
gemm_qkv_kernel(QKVArgs args)
{
    __shared__ GemmSmem sm;
    const int z = blockIdx.z;
    const float* bias = (z == 0) ? args.b0 : (z == 1) ? args.b1 : args.b2;
    __half* out       = (z == 0) ? args.o0 : (z == 1) ? args.o1 : args.o2;
    const int m0 = blockIdx.y * 128;
    const int n0 = blockIdx.x * 128;

    float acc[2][8][4];
    gemm_mainloop(g_xh, g_wh + (size_t)z * kC * kC, m0, n0, sm, acc);

    const int lid = threadIdx.x & 31;
    const int wid = threadIdx.x >> 5;
    const int wm  = (wid >> 1) * 32;
    const int wn  = (wid & 1) * 64;
    const int g   = lid >> 2;
    const int cp  = (lid & 3) * 2;
#pragma unroll
    for (int t = 0; t < 2; t++) {
        const int r0 = m0 + wm + 16 * t + g;
#pragma unroll
        for (int j = 0; j < 8; j++) {
            const int n = n0 + wn + 8 * j + cp;
            const float bx = bias[n], by = bias[n + 1];
            *(uint32_t*)&out[(size_t)r0 * kC + n] =
                f2h2(acc[t][j][0] + bx, acc[t][j][1] + by);
            *(uint32_t*)&out[(size_t)(r0 + 8) * kC + n] =
                f2h2(acc[t][j][2] + bx, acc[t][j][3] + by);
        }
    }
}

// Output GEMM: X = g_ctx (half), W = Wo (converted), out fp32 + bias + skip.
__global__ void __launch_bounds__(256)
gemm_o_kernel(const float* __restrict__ bias, const float* __restrict__ skip,
              float* __restrict__ out)
{
    __shared__ GemmSmem sm;
    const int m0 = blockIdx.y * 128;
    const int n0 = blockIdx.x * 128;

    float acc[2][8][4];
    gemm_mainloop(g_ctx, g_wh + (size_t)3 * kC * kC, m0, n0, sm, acc);

    const int lid = threadIdx.x & 31;
    const int wid = threadIdx.x >> 5;
    const int wm  = (wid >> 1) * 32;
    const int wn  = (wid & 1) * 64;
    const int g   = lid >> 2;
    const int cp  = (lid & 3) * 2;
#pragma unroll
    for (int t = 0; t < 2; t++) {
        const int r0 = m0 + wm + 16 * t + g;
#pragma unroll
        for (int j = 0; j < 8; j++) {
            const int n = n0 + wn + 8 * j + cp;
            const float bx = bias[n], by = bias[n + 1];
            float2 s0 = *(const float2*)&skip[(size_t)r0 * kC + n];
            float2 s1 = *(const float2*)&skip[(size_t)(r0 + 8) * kC + n];
            *(float2*)&out[(size_t)r0 * kC + n] =
                make_float2(acc[t][j][0] + bx + s0.x, acc[t][j][1] + by + s0.y);
            *(float2*)&out[(size_t)(r0 + 8) * kC + n] =
                make_float2(acc[t][j][2] + bx + s1.x, acc[t][j][3] + by + s1.y);
        }
    }
}

// ===========================================================================
// Tensor-core flash attention (f16 mma.sync, fp32 accumulate).
// CTA = 128 queries x one (b,h); 8 warps x 16 query rows; key tiles of 64.
// Q fragments hoisted to registers. P stays in registers (C->A repack).
// K/V tiles: 2-stage cp.async pipeline, one __syncthreads per tile.
// smem: 2 stages x (Ks[64][72] | Vs[64][72]) = 36864 B static.
// ===========================================================================
namespace {
constexpr int PQH = 72;
constexpr int ATTN_TILE_B = 128 * PQH * 2;   // 18432 B per stage (K+V)
}

__global__ void __launch_bounds__(256, 2)
attn_tc_kernel()
{
    __shared__ __half sm[2 * 128 * PQH];

    const int tid = threadIdx.x;
    const int lid = tid & 31;
    const int wid = tid >> 5;
    const int b   = blockIdx.z;
    const int h   = blockIdx.y;
    const int q0  = blockIdx.x * 128;

    const __half* Qg = g_q + (size_t)(b * kS + q0) * kC + h * kDH;
    const __half* Kg = g_k + (size_t)(b * kS) * kC + h * kDH;
    const __half* Vg = g_v + (size_t)(b * kS) * kC + h * kDH;

    // --- Stage Q through smem once; extract loop-invariant A fragments ---
#pragma unroll
    for (int t = 0; t < 4; t++) {
        int idx = tid + t * 256;          // 0..1023 16B-chunks
        int row = idx >> 3;               // 0..127
        int c8  = (idx & 7) * 8;
        *(uint4*)&sm[row * PQH + c8] = *(const uint4*)(Qg + (size_t)row * kC + c8);
    }
    __syncthreads();
    uint32_t qf[4][4];
    {
        const uint32_t aq = smem_u32(sm)
            + (wid * 16 + (lid & 15)) * (PQH * 2) + ((lid >> 4) << 4);
#pragma unroll
        for (int ks = 0; ks < 4; ks++)
            ldmatrix_x4(qf[ks][0], qf[ks][1], qf[ks][2], qf[ks][3], aq + ks * 32);
    }
    __syncthreads();   // done with Q staging; smem now K/V stages

    // cp.async destinations (stage 0): K rows 0..63, V rows 64..127
    const int lrow = tid >> 3;            // 0..31
    const int lc8  = (tid & 7) * 8;
    const uint32_t smu = smem_u32(sm);
    const uint32_t dK0 = smu + (lrow * PQH + lc8) * 2;
    const uint32_t dK1 = dK0 + 32 * PQH * 2;
    const uint32_t dV0 = smu + ((64 + lrow) * PQH + lc8) * 2;
    const uint32_t dV1 = dV0 + 32 * PQH * 2;
    const __half* gK0 = Kg + (size_t)lrow * kC + lc8;
    const __half* gK1 = Kg + (size_t)(32 + lrow) * kC + lc8;
    const __half* gV0 = Vg + (size_t)lrow * kC + lc8;
    const __half* gV1 = Vg + (size_t)(32 + lrow) * kC + lc8;

    // fragment addresses (stage 0)
    uint32_t bk[4], bvb[4];
#pragma unroll
    for (int jj = 0; jj < 4; jj++) {
        bk[jj] = smu
            + (16 * jj + ((lid >> 4) << 3) + (lid & 7)) * (PQH * 2)
            + (((lid >> 3) & 1) << 4);
        bvb[jj] = smu + 64 * PQH * 2
            + ((((lid >> 3) & 1) << 3) + (lid & 7)) * (PQH * 2)
            + (((lid >> 4) + 2 * jj) << 4);
    }

    float m_i[2] = {-INFINITY, -INFINITY};
    float l_i[2] = {0.f, 0.f};
    float accO[8][4];
#pragma unroll
    for (int j = 0; j < 8; j++)
#pragma unroll
        for (int c = 0; c < 4; c++) accO[j][c] = 0.f;
    const float cexp = 0.125f * 1.4426950408889634f;  // scale * log2(e)

    const int pr = wid * 16 + (lid >> 2);
    const int pc = (lid & 3) * 2;

    // prologue: issue K/V tile 0 into stage 0
    cp_async16(dK0, gK0);
    cp_async16(dK1, gK1);
    cp_async16(dV0, gV0);
    cp_async16(dV1, gV1);
    CP_COMMIT();

#pragma unroll 1
    for (int i = 0; i < kS / 64; i++) {
        CP_WAIT0();
        __syncthreads();
        const uint32_t boff = (uint32_t)(i & 1) * ATTN_TILE_B;

        if (i + 1 < kS / 64) {
            const uint32_t noff = (uint32_t)((i + 1) & 1) * ATTN_TILE_B;
            const size_t go = (size_t)(i + 1) * 64 * kC;
            cp_async16(dK0 + noff, gK0 + go);
            cp_async16(dK1 + noff, gK1 + go);
            cp_async16(dV0 + noff, gV0 + go);
            cp_async16(dV1 + noff, gV1 + go);
            CP_COMMIT();
        }

        // S = Q K^T   (4 k16 steps over d=64)
        float s[8][4];
#pragma unroll
        for (int j = 0; j < 8; j++)
#pragma unroll
            for (int c = 0; c < 4; c++) s[j][c] = 0.f;
#pragma unroll
        for (int ks = 0; ks < 4; ks++) {
            uint32_t bf[8][2];
#pragma unroll
            for (int jj = 0; jj < 4; jj++) {
                uint32_t r0, r1, r2, r3;
                ldmatrix_x4(r0, r1, r2, r3, bk[jj] + boff + ks * 32);
                bf[2 * jj][0] = r0;  bf[2 * jj][1] = r1;
                bf[2 * jj + 1][0] = r2;  bf[2 * jj + 1][1] = r3;
            }
#pragma unroll
            for (int j = 0; j < 8; j++)
                mma_f16(s[j], qf[ks][0], qf[ks][1], qf[ks][2], qf[ks][3],
                        bf[j][0], bf[j][1]);
        }

        // online softmax (half 0: row pr; half 1: row pr+8)
#pragma unroll
        for (int hf = 0; hf < 2; hf++) {
            const int c0 = 2 * hf, c1 = 2 * hf + 1;
            float mx = fmaxf(s[0][c0], s[0][c1]);
#pragma unroll
            for (int j = 1; j < 8; j++)
                mx = fmaxf(mx, fmaxf(s[j][c0], s[j][c1]));
            mx = fmaxf(mx, __shfl_xor_sync(0xffffffffu, mx, 1));
            mx = fmaxf(mx, __shfl_xor_sync(0xffffffffu, mx, 2));
            float mnew = fmaxf(m_i[hf], mx);
            float alpha = exp2f((m_i[hf] - mnew) * cexp);
            float rs = 0.f;
#pragma unroll
            for (int j = 0; j < 8; j++) {
                s[j][c0] = exp2f((s[j][c0] - mnew) * cexp);
                s[j][c1] = exp2f((s[j][c1] - mnew) * cexp);
                rs += s[j][c0] + s[j][c1];
            }
            rs += __shfl_xor_sync(0xffffffffu, rs, 1);
            rs += __shfl_xor_sync(0xffffffffu, rs, 2);
            l_i[hf] = l_i[hf] * alpha + rs;
            m_i[hf] = mnew;
#pragma unroll
            for (int j = 0; j < 8; j++) {
                accO[j][c0] *= alpha;
                accO[j][c1] *= alpha;
            }
        }

        // O += P * V : P's A-fragments come straight from S's C-fragments.
#pragma unroll
        for (int ks = 0; ks < 4; ks++) {
            const uint32_t a0 = f2h2(s[2 * ks][0],     s[2 * ks][1]);
            const uint32_t a1 = f2h2(s[2 * ks][2],     s[2 * ks][3]);
            const uint32_t a2 = f2h2(s[2 * ks + 1][0], s[2 * ks + 1][1]);
            const uint32_t a3 = f2h2(s[2 * ks + 1][2], s[2 * ks + 1][3]);
            uint32_t bf[8][2];
#pragma unroll
            for (int jj = 0; jj < 4; jj++) {
                uint32_t r0, r1, r2, r3;
                ldmatrix_x4_trans(r0, r1, r2, r3,
                                  bvb[jj] + boff + ks * 16 * (PQH * 2));
                bf[2 * jj][0] = r0;  bf[2 * jj][1] = r1;
                bf[2 * jj + 1][0] = r2;  bf[2 * jj + 1][1] = r3;
            }
#pragma unroll
            for (int j = 0; j < 8; j++)
                mma_f16(accO[j], a0, a1, a2, a3, bf[j][0], bf[j][1]);
        }
    }

    // normalize + write ctx (fp16)
    {
        const float inv0 = 1.f / l_i[0];
        const float inv1 = 1.f / l_i[1];
        __half* O0 = g_ctx + (size_t)(b * kS + q0 + pr) * kC + h * kDH;
        __half* O1 = O0 + (size_t)8 * kC;
#pragma unroll
        for (int j = 0; j < 8; j++) {
            const int c = 8 * j + pc;
            *(uint32_t*)&O0[c] = f2h2(accO[j][0] * inv0, accO[j][1] * inv0);
            *(uint32_t*)&O1[c] = f2h2(accO[j][2] * inv1, accO[j][3] * inv1);
        }
    }
}

// ---------------------------------------------------------------------------
// Launch
// ---------------------------------------------------------------------------
extern "C" void kernel_launch(void* const* d_in, const int* in_sizes, int n_in,
                              void* d_out, int out_size)
{
    (void)in_sizes; (void)n_in; (void)out_size;
    const float* x    = (const float*)d_in[0];
    const float* skip = (const float*)d_in[1];
    const float* Wq   = (const float*)d_in[2];
    const float* bq   = (const float*)d_in[3];
    const float* Wk   = (const float*)d_in[4];
    const float* bk   = (const float*)d_in[5];
    const float* Wv   = (const float*)d_in[6];
    const float* bv   = (const float*)d_in[7];
    const float* Wo   = (const float*)d_in[8];
    const float* bo   = (const float*)d_in[9];
    float* out = (float*)d_out;

    __half *qb, *kb, *vb;
    cudaGetSymbolAddress((void**)&qb, g_q);
    cudaGetSymbolAddress((void**)&kb, g_k);
    cudaGetSymbolAddress((void**)&vb, g_v);

    // 1) convert x + weights to fp16
    CvtArgs ca; ca.src[0] = x; ca.src[1] = Wq; ca.src[2] = Wk;
    ca.src[3] = Wv; ca.src[4] = Wo;
    convert_kernel<<<(NX4 + 4 * NW4) / 256, 256>>>(ca);

    // 2) fused QKV projections
    QKVArgs qkv = { bq, bk, bv, qb, kb, vb };
    gemm_qkv_kernel<<<dim3(kC / 128, kM / 128, 3), 256>>>(qkv);

    // 3) attention
    attn_tc_kernel<<<dim3(kS / 128, kH, kB), 256>>>();

    // 4) output projection + bias + skip
    gemm_o_kernel<<<dim3(kC / 128, kM / 128, 1), 256>>>(bo, skip, out);
}

// round 11
// speedup vs baseline: 9.9336x; 1.0102x over previous
#include <cuda_runtime.h>
#include <cuda_fp16.h>
#include <math.h>
#include <stdint.h>

// Problem constants: B=8, S=1024, C=512, H=8, DH=64
namespace {
constexpr int kB  = 8;
constexpr int kS  = 1024;
constexpr int kC  = 512;
constexpr int kH  = 8;
constexpr int kDH = 64;
constexpr int kM  = kB * kS;   // 8192 rows
}

// Scratch (allocation-free device globals), all fp16.
__device__ __half g_xh[kM * kC];        // x converted
__device__ __half g_wh[4 * kC * kC];    // Wq,Wk,Wv,Wo converted
__device__ __half g_q[kM * kC];
__device__ __half g_k[kM * kC];
__device__ __half g_v[kM * kC];
__device__ __half g_ctx[kM * kC];

// ===========================================================================
// Helpers (base sm_103 target; tcgen05 is ptxas-rejected on this harness)
// ===========================================================================
__device__ __forceinline__ uint32_t smem_u32(const void* p) {
    uint32_t a;
    asm("{ .reg .u64 t; cvta.to.shared.u64 t, %1; cvt.u32.u64 %0, t; }"
        : "=r"(a) : "l"(p));
    return a;
}

__device__ __forceinline__ uint32_t f2h2(float lo, float hi) {
    __half2 h = __float22half2_rn(make_float2(lo, hi));
    return *reinterpret_cast<uint32_t*>(&h);
}

__device__ __forceinline__ void cp_async16(uint32_t dst, const void* src) {
    asm volatile("cp.async.cg.shared.global [%0], [%1], 16;"
                 :: "r"(dst), "l"(src));
}
#define CP_COMMIT() asm volatile("cp.async.commit_group;" ::: "memory")
#define CP_WAIT0()  asm volatile("cp.async.wait_group 0;" ::: "memory")

__device__ __forceinline__ void ldmatrix_x4(uint32_t& r0, uint32_t& r1,
                                            uint32_t& r2, uint32_t& r3,
                                            uint32_t addr) {
    asm volatile("ldmatrix.sync.aligned.m8n8.x4.shared.b16 {%0,%1,%2,%3}, [%4];"
                 : "=r"(r0), "=r"(r1), "=r"(r2), "=r"(r3) : "r"(addr));
}

__device__ __forceinline__ void ldmatrix_x4_trans(uint32_t& r0, uint32_t& r1,
                                                  uint32_t& r2, uint32_t& r3,
                                                  uint32_t addr) {
    asm volatile("ldmatrix.sync.aligned.m8n8.x4.trans.shared.b16 {%0,%1,%2,%3}, [%4];"
                 : "=r"(r0), "=r"(r1), "=r"(r2), "=r"(r3) : "r"(addr));
}

// D(16x8) += A(16x16) * B(16x8), f16 inputs, fp32 accumulate.
__device__ __forceinline__ void mma_f16(float* c, uint32_t a0, uint32_t a1,
                                        uint32_t a2, uint32_t a3,
                                        uint32_t b0, uint32_t b1) {
    asm volatile(
        "mma.sync.aligned.m16n8k16.row.col.f32.f16.f16.f32 "
        "{%0,%1,%2,%3}, {%4,%5,%6,%7}, {%8,%9}, {%0,%1,%2,%3};"
        : "+f"(c[0]), "+f"(c[1]), "+f"(c[2]), "+f"(c[3])
        : "r"(a0), "r"(a1), "r"(a2), "r"(a3), "r"(b0), "r"(b1));
}

// ===========================================================================
// fp32 -> fp16 pre-convert: x (kM*kC) and 4 weight matrices (kC*kC each).
// ===========================================================================
struct CvtArgs { const float* src[5]; };

namespace {
constexpr int NX4 = kM * kC / 4;   // float4 count of x
constexpr int NW4 = kC * kC / 4;   // float4 count of one W
}

__global__ void __launch_bounds__(256)
convert_kernel(CvtArgs a)
{
    int i = blockIdx.x * 256 + threadIdx.x;   // float4 index
    const float* src;
    __half* dst;
    int off;
    if (i < NX4) {
        src = a.src[0]; dst = g_xh; off = i;
    } else {
        int r = (i - NX4) >> 16;              // / NW4 (65536)
        off   = (i - NX4) & (NW4 - 1);
        src = a.src[1 + r]; dst = g_wh + r * kC * kC;
    }
    float4 v = ((const float4*)src)[off];
    uint2 w;
    w.x = f2h2(v.x, v.y);
    w.y = f2h2(v.z, v.w);
    *(uint2*)&dst[off * 4] = w;
}

// ===========================================================================
// f16 mma.sync GEMM core: acc[m,n] = sum_k X[m,k]*W[n,k]
// CTA tile 64(m) x 128(n), BK=32, 8 warps in 2(m) x 4(n), warp tile 32x32.
// 2x the warp count of the old 128x128 tiling -> ~28 warps/SM; 3 CTAs/SM cap.
// 2-stage cp.async pipeline, one __syncthreads per slab.
// smem pitch 40 halves (80 B): conflict-free ldmatrix.
// ===========================================================================
namespace {
constexpr int PKH = 40;
constexpr int GEMM_A_TILE_B = 64  * PKH * 2;   // 5120 B per stage
constexpr int GEMM_B_TILE_B = 128 * PKH * 2;   // 10240 B per stage
}

struct GemmSmem { __half A[2][64 * PKH]; __half B[2][128 * PKH]; };  // 30 KB

// Runs the mainloop; leaves results in acc[2][4][4].
__device__ __forceinline__ void gemm_mainloop(
    const __half* __restrict__ X, const __half* __restrict__ W,
    int m0, int n0, GemmSmem& sm, float acc[2][4][4])
{
    const int tid = threadIdx.x;
    const int lid = tid & 31;
    const int wid = tid >> 5;
    const int wm  = (wid >> 2) * 32;   // 0 or 32
    const int wn  = (wid & 3) * 32;    // 0,32,64,96

    // loader: A 1 chunk, B 2 chunks per thread per slab
    const int lrow = tid >> 2;             // 0..63
    const int lc   = (tid & 3) * 8;        // half offset of 16B chunk

    const uint32_t sAu = smem_u32(sm.A[0]);
    const uint32_t sBu = smem_u32(sm.B[0]);

    const uint32_t dA0 = sAu + (lrow * PKH + lc) * 2;
    const uint32_t dB0 = sBu + (lrow * PKH + lc) * 2;
    const uint32_t dB1 = dB0 + 64 * PKH * 2;

    const __half* gA0 = X + (size_t)(m0 + lrow) * kC + lc;
    const __half* gB0 = W + (size_t)(n0 + lrow) * kC + lc;
    const __half* gB1 = W + (size_t)(n0 + 64 + lrow) * kC + lc;

    // ldmatrix fragment addresses (stage 0)
    uint32_t a_addr[2], b_addr[2];
#pragma unroll
    for (int t = 0; t < 2; t++)
        a_addr[t] = sAu + (wm + 16 * t + (lid & 15)) * (PKH * 2) + ((lid >> 4) << 4);
#pragma unroll
    for (int jj = 0; jj < 2; jj++)
        b_addr[jj] = sBu + (wn + 16 * jj + ((lid >> 4) << 3) + (lid & 7)) * (PKH * 2)
                   + (((lid >> 3) & 1) << 4);

#pragma unroll
    for (int t = 0; t < 2; t++)
#pragma unroll
        for (int j = 0; j < 4; j++)
#pragma unroll
            for (int c = 0; c < 4; c++) acc[t][j][c] = 0.f;

    // prologue: issue slab 0 into stage 0
    cp_async16(dA0, gA0);
    cp_async16(dB0, gB0);
    cp_async16(dB1, gB1);
    CP_COMMIT();

#pragma unroll 1
    for (int s = 0; s < kC / 32; s++) {
        CP_WAIT0();
        __syncthreads();
        const uint32_t aoff = (uint32_t)(s & 1) * GEMM_A_TILE_B;
        const uint32_t boff = (uint32_t)(s & 1) * GEMM_B_TILE_B;

        if (s + 1 < kC / 32) {
            const uint32_t naoff = (uint32_t)((s + 1) & 1) * GEMM_A_TILE_B;
            const uint32_t nboff = (uint32_t)((s + 1) & 1) * GEMM_B_TILE_B;
            const int k0 = (s + 1) * 32;
            cp_async16(dA0 + naoff, gA0 + k0);
            cp_async16(dB0 + nboff, gB0 + k0);
            cp_async16(dB1 + nboff, gB1 + k0);
            CP_COMMIT();
        }

#pragma unroll
        for (int ks = 0; ks < 2; ks++) {
            const uint32_t ko = ks * 32;   // 16 halves = 32 B
            uint32_t a[2][4];
#pragma unroll
            for (int t = 0; t < 2; t++)
                ldmatrix_x4(a[t][0], a[t][1], a[t][2], a[t][3],
                            a_addr[t] + aoff + ko);
            uint32_t b[4][2];
#pragma unroll
            for (int jj = 0; jj < 2; jj++) {
                uint32_t r0, r1, r2, r3;
                ldmatrix_x4(r0, r1, r2, r3, b_addr[jj] + boff + ko);
                b[2 * jj][0] = r0;  b[2 * jj][1] = r1;
                b[2 * jj + 1][0] = r2;  b[2 * jj + 1][1] = r3;
            }
#pragma unroll
            for (int t = 0; t < 2; t++)
#pragma unroll
                for (int j = 0; j < 4; j++)
                    mma_f16(acc[t][j], a[t][0], a[t][1], a[t][2], a[t][3],
                            b[j][0], b[j][1]);
        }
    }
}

// QKV fused GEMM: z selects (W, bias, half-out). X = g_xh.
struct QKVArgs { const float *b0, *b1, *b2; __half *o0, *o1, *o2; };

__global__ void __launch_bounds__(256, 3)
gemm_qkv_kernel(QKVArgs args)
{
    __shared__ GemmSmem sm;
    const int z = blockIdx.z;
    const float* bias = (z == 0) ? args.b0 : (z == 1) ? args.b1 : args.b2;
    __half* out       = (z == 0) ? args.o0 : (z == 1) ? args.o1 : args.o2;
    const int m0 = blockIdx.y * 64;
    const int n0 = blockIdx.x * 128;

    float acc[2][4][4];
    gemm_mainloop(g_xh, g_wh + (size_t)z * kC * kC, m0, n0, sm, acc);

    const int lid = threadIdx.x & 31;
    const int wid = threadIdx.x >> 5;
    const int wm  = (wid >> 2) * 32;
    const int wn  = (wid & 3) * 32;
    const int g   = lid >> 2;
    const int cp  = (lid & 3) * 2;
#pragma unroll
    for (int t = 0; t < 2; t++) {
        const int r0 = m0 + wm + 16 * t + g;
#pragma unroll
        for (int j = 0; j < 4; j++) {
            const int n = n0 + wn + 8 * j + cp;
            const float bx = bias[n], by = bias[n + 1];
            *(uint32_t*)&out[(size_t)r0 * kC + n] =
                f2h2(acc[t][j][0] + bx, acc[t][j][1] + by);
            *(uint32_t*)&out[(size_t)(r0 + 8) * kC + n] =
                f2h2(acc[t][j][2] + bx, acc[t][j][3] + by);
        }
    }
}

// Output GEMM: X = g_ctx (half), W = Wo (converted), out fp32 + bias + skip.
__global__ void __launch_bounds__(256, 3)
gemm_o_kernel(const float* __restrict__ bias, const float* __restrict__ skip,
              float* __restrict__ out)
{
    __shared__ GemmSmem sm;
    const int m0 = blockIdx.y * 64;
    const int n0 = blockIdx.x * 128;

    float acc[2][4][4];
    gemm_mainloop(g_ctx, g_wh + (size_t)3 * kC * kC, m0, n0, sm, acc);

    const int lid = threadIdx.x & 31;
    const int wid = threadIdx.x >> 5;
    const int wm  = (wid >> 2) * 32;
    const int wn  = (wid & 3) * 32;
    const int g   = lid >> 2;
    const int cp  = (lid & 3) * 2;
#pragma unroll
    for (int t = 0; t < 2; t++) {
        const int r0 = m0 + wm + 16 * t + g;
#pragma unroll
        for (int j = 0; j < 4; j++) {
            const int n = n0 + wn + 8 * j + cp;
            const float bx = bias[n], by = bias[n + 1];
            float2 s0 = *(const float2*)&skip[(size_t)r0 * kC + n];
            float2 s1 = *(const float2*)&skip[(size_t)(r0 + 8) * kC + n];
            *(float2*)&out[(size_t)r0 * kC + n] =
                make_float2(acc[t][j][0] + bx + s0.x, acc[t][j][1] + by + s0.y);
            *(float2*)&out[(size_t)(r0 + 8) * kC + n] =
                make_float2(acc[t][j][2] + bx + s1.x, acc[t][j][3] + by + s1.y);
        }
    }
}

// ===========================================================================
// Tensor-core flash attention (f16 mma.sync, fp32 accumulate).
// CTA = 128 queries x one (b,h); 8 warps x 16 query rows; key tiles of 64.
// Q fragments hoisted to registers. P stays in registers (C->A repack).
// K/V tiles: 2-stage cp.async pipeline, one __syncthreads per tile.
// smem: 2 stages x (Ks[64][72] | Vs[64][72]) = 36864 B static.
// ===========================================================================
namespace {
constexpr int PQH = 72;
constexpr int ATTN_TILE_B = 128 * PQH * 2;   // 18432 B per stage (K+V)
}

__global__ void __launch_bounds__(256, 2)
attn_tc_kernel()
{
    __shared__ __half sm[2 * 128 * PQH];

    const int tid = threadIdx.x;
    const int lid = tid & 31;
    const int wid = tid >> 5;
    const int b   = blockIdx.z;
    const int h   = blockIdx.y;
    const int q0  = blockIdx.x * 128;

    const __half* Qg = g_q + (size_t)(b * kS + q0) * kC + h * kDH;
    const __half* Kg = g_k + (size_t)(b * kS) * kC + h * kDH;
    const __half* Vg = g_v + (size_t)(b * kS) * kC + h * kDH;

    // --- Stage Q through smem once; extract loop-invariant A fragments ---
#pragma unroll
    for (int t = 0; t < 4; t++) {
        int idx = tid + t * 256;          // 0..1023 16B-chunks
        int row = idx >> 3;               // 0..127
        int c8  = (idx & 7) * 8;
        *(uint4*)&sm[row * PQH + c8] = *(const uint4*)(Qg + (size_t)row * kC + c8);
    }
    __syncthreads();
    uint32_t qf[4][4];
    {
        const uint32_t aq = smem_u32(sm)
            + (wid * 16 + (lid & 15)) * (PQH * 2) + ((lid >> 4) << 4);
#pragma unroll
        for (int ks = 0; ks < 4; ks++)
            ldmatrix_x4(qf[ks][0], qf[ks][1], qf[ks][2], qf[ks][3], aq + ks * 32);
    }
    __syncthreads();   // done with Q staging; smem now K/V stages

    // cp.async destinations (stage 0): K rows 0..63, V rows 64..127
    const int lrow = tid >> 3;            // 0..31
    const int lc8  = (tid & 7) * 8;
    const uint32_t smu = smem_u32(sm);
    const uint32_t dK0 = smu + (lrow * PQH + lc8) * 2;
    const uint32_t dK1 = dK0 + 32 * PQH * 2;
    const uint32_t dV0 = smu + ((64 + lrow) * PQH + lc8) * 2;
    const uint32_t dV1 = dV0 + 32 * PQH * 2;
    const __half* gK0 = Kg + (size_t)lrow * kC + lc8;
    const __half* gK1 = Kg + (size_t)(32 + lrow) * kC + lc8;
    const __half* gV0 = Vg + (size_t)lrow * kC + lc8;
    const __half* gV1 = Vg + (size_t)(32 + lrow) * kC + lc8;

    // fragment addresses (stage 0)
    uint32_t bk[4], bvb[4];
#pragma unroll
    for (int jj = 0; jj < 4; jj++) {
        bk[jj] = smu
            + (16 * jj + ((lid >> 4) << 3) + (lid & 7)) * (PQH * 2)
            + (((lid >> 3) & 1) << 4);
        bvb[jj] = smu + 64 * PQH * 2
            + ((((lid >> 3) & 1) << 3) + (lid & 7)) * (PQH * 2)
            + (((lid >> 4) + 2 * jj) << 4);
    }

    float m_i[2] = {-INFINITY, -INFINITY};
    float l_i[2] = {0.f, 0.f};
    float accO[8][4];
#pragma unroll
    for (int j = 0; j < 8; j++)
#pragma unroll
        for (int c = 0; c < 4; c++) accO[j][c] = 0.f;
    const float cexp = 0.125f * 1.4426950408889634f;  // scale * log2(e)

    const int pr = wid * 16 + (lid >> 2);
    const int pc = (lid & 3) * 2;

    // prologue: issue K/V tile 0 into stage 0
    cp_async16(dK0, gK0);
    cp_async16(dK1, gK1);
    cp_async16(dV0, gV0);
    cp_async16(dV1, gV1);
    CP_COMMIT();

#pragma unroll 1
    for (int i = 0; i < kS / 64; i++) {
        CP_WAIT0();
        __syncthreads();
        const uint32_t boff = (uint32_t)(i & 1) * ATTN_TILE_B;

        if (i + 1 < kS / 64) {
            const uint32_t noff = (uint32_t)((i + 1) & 1) * ATTN_TILE_B;
            const size_t go = (size_t)(i + 1) * 64 * kC;
            cp_async16(dK0 + noff, gK0 + go);
            cp_async16(dK1 + noff, gK1 + go);
            cp_async16(dV0 + noff, gV0 + go);
            cp_async16(dV1 + noff, gV1 + go);
            CP_COMMIT();
        }

        // S = Q K^T   (4 k16 steps over d=64)
        float s[8][4];
#pragma unroll
        for (int j = 0; j < 8; j++)
#pragma unroll
            for (int c = 0; c < 4; c++) s[j][c] = 0.f;
#pragma unroll
        for (int ks = 0; ks < 4; ks++) {
            uint32_t bf[8][2];
#pragma unroll
            for (int jj = 0; jj < 4; jj++) {
                uint32_t r0, r1, r2, r3;
                ldmatrix_x4(r0, r1, r2, r3, bk[jj] + boff + ks * 32);
                bf[2 * jj][0] = r0;  bf[2 * jj][1] = r1;
                bf[2 * jj + 1][0] = r2;  bf[2 * jj + 1][1] = r3;
            }
#pragma unroll
            for (int j = 0; j < 8; j++)
                mma_f16(s[j], qf[ks][0], qf[ks][1], qf[ks][2], qf[ks][3],
                        bf[j][0], bf[j][1]);
        }

        // online softmax (half 0: row pr; half 1: row pr+8)
#pragma unroll
        for (int hf = 0; hf < 2; hf++) {
            const int c0 = 2 * hf, c1 = 2 * hf + 1;
            float mx = fmaxf(s[0][c0], s[0][c1]);
#pragma unroll
            for (int j = 1; j < 8; j++)
                mx = fmaxf(mx, fmaxf(s[j][c0], s[j][c1]));
            mx = fmaxf(mx, __shfl_xor_sync(0xffffffffu, mx, 1));
            mx = fmaxf(mx, __shfl_xor_sync(0xffffffffu, mx, 2));
            float mnew = fmaxf(m_i[hf], mx);
            float alpha = exp2f((m_i[hf] - mnew) * cexp);
            float rs = 0.f;
#pragma unroll
            for (int j = 0; j < 8; j++) {
                s[j][c0] = exp2f((s[j][c0] - mnew) * cexp);
                s[j][c1] = exp2f((s[j][c1] - mnew) * cexp);
                rs += s[j][c0] + s[j][c1];
            }
            rs += __shfl_xor_sync(0xffffffffu, rs, 1);
            rs += __shfl_xor_sync(0xffffffffu, rs, 2);
            l_i[hf] = l_i[hf] * alpha + rs;
            m_i[hf] = mnew;
#pragma unroll
            for (int j = 0; j < 8; j++) {
                accO[j][c0] *= alpha;
                accO[j][c1] *= alpha;
            }
        }

        // O += P * V : P's A-fragments come straight from S's C-fragments.
#pragma unroll
        for (int ks = 0; ks < 4; ks++) {
            const uint32_t a0 = f2h2(s[2 * ks][0],     s[2 * ks][1]);
            const uint32_t a1 = f2h2(s[2 * ks][2],     s[2 * ks][3]);
            const uint32_t a2 = f2h2(s[2 * ks + 1][0], s[2 * ks + 1][1]);
            const uint32_t a3 = f2h2(s[2 * ks + 1][2], s[2 * ks + 1][3]);
            uint32_t bf[8][2];
#pragma unroll
            for (int jj = 0; jj < 4; jj++) {
                uint32_t r0, r1, r2, r3;
                ldmatrix_x4_trans(r0, r1, r2, r3,
                                  bvb[jj] + boff + ks * 16 * (PQH * 2));
                bf[2 * jj][0] = r0;  bf[2 * jj][1] = r1;
                bf[2 * jj + 1][0] = r2;  bf[2 * jj + 1][1] = r3;
            }
#pragma unroll
            for (int j = 0; j < 8; j++)
                mma_f16(accO[j], a0, a1, a2, a3, bf[j][0], bf[j][1]);
        }
    }

    // normalize + write ctx (fp16)
    {
        const float inv0 = 1.f / l_i[0];
        const float inv1 = 1.f / l_i[1];
        __half* O0 = g_ctx + (size_t)(b * kS + q0 + pr) * kC + h * kDH;
        __half* O1 = O0 + (size_t)8 * kC;
#pragma unroll
        for (int j = 0; j < 8; j++) {
            const int c = 8 * j + pc;
            *(uint32_t*)&O0[c] = f2h2(accO[j][0] * inv0, accO[j][1] * inv0);
            *(uint32_t*)&O1[c] = f2h2(accO[j][2] * inv1, accO[j][3] * inv1);
        }
    }
}

// ---------------------------------------------------------------------------
// Launch
// ---------------------------------------------------------------------------
extern "C" void kernel_launch(void* const* d_in, const int* in_sizes, int n_in,
                              void* d_out, int out_size)
{
    (void)in_sizes; (void)n_in; (void)out_size;
    const float* x    = (const float*)d_in[0];
    const float* skip = (const float*)d_in[1];
    const float* Wq   = (const float*)d_in[2];
    const float* bq   = (const float*)d_in[3];
    const float* Wk   = (const float*)d_in[4];
    const float* bk   = (const float*)d_in[5];
    const float* Wv   = (const float*)d_in[6];
    const float* bv   = (const float*)d_in[7];
    const float* Wo   = (const float*)d_in[8];
    const float* bo   = (const float*)d_in[9];
    float* out = (float*)d_out;

    __half *qb, *kb, *vb;
    cudaGetSymbolAddress((void**)&qb, g_q);
    cudaGetSymbolAddress((void**)&kb, g_k);
    cudaGetSymbolAddress((void**)&vb, g_v);

    // 1) convert x + weights to fp16
    CvtArgs ca; ca.src[0] = x; ca.src[1] = Wq; ca.src[2] = Wk;
    ca.src[3] = Wv; ca.src[4] = Wo;
    convert_kernel<<<(NX4 + 4 * NW4) / 256, 256>>>(ca);

    // 2) fused QKV projections (CTA tile 64x128)
    QKVArgs qkv = { bq, bk, bv, qb, kb, vb };
    gemm_qkv_kernel<<<dim3(kC / 128, kM / 64, 3), 256>>>(qkv);

    // 3) attention
    attn_tc_kernel<<<dim3(kS / 128, kH, kB), 256>>>();

    // 4) output projection + bias + skip (CTA tile 64x128)
    gemm_o_kernel<<<dim3(kC / 128, kM / 64, 1), 256>>>(bo, skip, out);
}

// round 12
// speedup vs baseline: 9.9515x; 1.0018x over previous
#include <cuda_runtime.h>
#include <cuda_fp16.h>
#include <math.h>
#include <stdint.h>

// Problem constants: B=8, S=1024, C=512, H=8, DH=64
namespace {
constexpr int kB  = 8;
constexpr int kS  = 1024;
constexpr int kC  = 512;
constexpr int kH  = 8;
constexpr int kDH = 64;
constexpr int kM  = kB * kS;   // 8192 rows
}

// Scratch (allocation-free device globals), all fp16.
__device__ __half g_xh[kM * kC];        // x converted
__device__ __half g_wh[4 * kC * kC];    // Wq,Wk,Wv,Wo converted
__device__ __half g_q[kM * kC];
__device__ __half g_k[kM * kC];
__device__ __half g_v[kM * kC];
__device__ __half g_ctx[kM * kC];

// ===========================================================================
// Helpers (base sm_103 target; tcgen05 is ptxas-rejected on this harness)
// ===========================================================================
__device__ __forceinline__ uint32_t smem_u32(const void* p) {
    uint32_t a;
    asm("{ .reg .u64 t; cvta.to.shared.u64 t, %1; cvt.u32.u64 %0, t; }"
        : "=r"(a) : "l"(p));
    return a;
}

__device__ __forceinline__ uint32_t f2h2(float lo, float hi) {
    __half2 h = __float22half2_rn(make_float2(lo, hi));
    return *reinterpret_cast<uint32_t*>(&h);
}

__device__ __forceinline__ void cp_async16(uint32_t dst, const void* src) {
    asm volatile("cp.async.cg.shared.global [%0], [%1], 16;"
                 :: "r"(dst), "l"(src));
}
#define CP_COMMIT() asm volatile("cp.async.commit_group;" ::: "memory")
#define CP_WAIT1()  asm volatile("cp.async.wait_group 1;" ::: "memory")
#define CP_WAIT2()  asm volatile("cp.async.wait_group 2;" ::: "memory")

__device__ __forceinline__ void ldmatrix_x4(uint32_t& r0, uint32_t& r1,
                                            uint32_t& r2, uint32_t& r3,
                                            uint32_t addr) {
    asm volatile("ldmatrix.sync.aligned.m8n8.x4.shared.b16 {%0,%1,%2,%3}, [%4];"
                 : "=r"(r0), "=r"(r1), "=r"(r2), "=r"(r3) : "r"(addr));
}

__device__ __forceinline__ void ldmatrix_x4_trans(uint32_t& r0, uint32_t& r1,
                                                  uint32_t& r2, uint32_t& r3,
                                                  uint32_t addr) {
    asm volatile("ldmatrix.sync.aligned.m8n8.x4.trans.shared.b16 {%0,%1,%2,%3}, [%4];"
                 : "=r"(r0), "=r"(r1), "=r"(r2), "=r"(r3) : "r"(addr));
}

// D(16x8) += A(16x16) * B(16x8), f16 inputs, fp32 accumulate.
__device__ __forceinline__ void mma_f16(float* c, uint32_t a0, uint32_t a1,
                                        uint32_t a2, uint32_t a3,
                                        uint32_t b0, uint32_t b1) {
    asm volatile(
        "mma.sync.aligned.m16n8k16.row.col.f32.f16.f16.f32 "
        "{%0,%1,%2,%3}, {%4,%5,%6,%7}, {%8,%9}, {%0,%1,%2,%3};"
        : "+f"(c[0]), "+f"(c[1]), "+f"(c[2]), "+f"(c[3])
        : "r"(a0), "r"(a1), "r"(a2), "r"(a3), "r"(b0), "r"(b1));
}

// ===========================================================================
// fp32 -> fp16 pre-convert: x (kM*kC) and 4 weight matrices (kC*kC each).
// ===========================================================================
struct CvtArgs { const float* src[5]; };

namespace {
constexpr int NX4 = kM * kC / 4;   // float4 count of x
constexpr int NW4 = kC * kC / 4;   // float4 count of one W
}

__global__ void __launch_bounds__(256)
convert_kernel(CvtArgs a)
{
    int i = blockIdx.x * 256 + threadIdx.x;   // float4 index
    const float* src;
    __half* dst;
    int off;
    if (i < NX4) {
        src = a.src[0]; dst = g_xh; off = i;
    } else {
        int r = (i - NX4) >> 16;              // / NW4 (65536)
        off   = (i - NX4) & (NW4 - 1);
        src = a.src[1 + r]; dst = g_wh + r * kC * kC;
    }
    float4 v = ((const float4*)src)[off];
    uint2 w;
    w.x = f2h2(v.x, v.y);
    w.y = f2h2(v.z, v.w);
    *(uint2*)&dst[off * 4] = w;
}

// ===========================================================================
// f16 mma.sync GEMM core: acc[m,n] = sum_k X[m,k]*W[n,k]
// CTA 128x128, BK=32 (2 x k16 per slab, 16 slabs), 8 warps 32(m) x 64(n).
// 4-stage cp.async pipeline, wait_group 2, always-commit: copy for slab s
// is issued 3 compute-sections before use -> L2 latency fully hidden.
// smem (dynamic): 4 stages x (A[128][40] | B[128][40]) = 81920 B.
// Pitch 40 halves (80 B): conflict-free ldmatrix.
// ===========================================================================
namespace {
constexpr int PKH = 40;
constexpr int GEMM_MAT_H    = 128 * PKH;           // halves per matrix
constexpr int GEMM_STAGE_B  = 2 * GEMM_MAT_H * 2;  // 20480 B per stage
constexpr int GEMM_SMEM     = 4 * GEMM_STAGE_B;    // 81920 B
constexpr int NSLAB = kC / 32;                     // 16
}

// Runs the mainloop; leaves results in acc[2][8][4].
__device__ __forceinline__ void gemm_mainloop(
    const __half* __restrict__ X, const __half* __restrict__ W,
    int m0, int n0, __half* dsm, float acc[2][8][4])
{
    const int tid = threadIdx.x;
    const int lid = tid & 31;
    const int wid = tid >> 5;
    const int wm  = (wid >> 1) * 32;
    const int wn  = (wid & 1) * 64;

    // loader: 2 16B-chunks per matrix per thread per slab
    const int lrow0 = tid >> 2;            // 0..63
    const int lc    = (tid & 3) * 8;       // half offset of 16B chunk

    const uint32_t sAu = smem_u32(dsm);                      // stage 0 A
    const uint32_t sBu = sAu + GEMM_MAT_H * 2;               // stage 0 B

    const uint32_t dA0 = sAu + (lrow0 * PKH + lc) * 2;
    const uint32_t dA1 = dA0 + 64 * PKH * 2;
    const uint32_t dB0 = sBu + (lrow0 * PKH + lc) * 2;
    const uint32_t dB1 = dB0 + 64 * PKH * 2;

    const __half* gA0 = X + (size_t)(m0 + lrow0) * kC + lc;
    const __half* gA1 = X + (size_t)(m0 + 64 + lrow0) * kC + lc;
    const __half* gB0 = W + (size_t)(n0 + lrow0) * kC + lc;
    const __half* gB1 = W + (size_t)(n0 + 64 + lrow0) * kC + lc;

    // ldmatrix fragment addresses (stage 0)
    uint32_t a_addr[2], b_addr[4];
#pragma unroll
    for (int t = 0; t < 2; t++)
        a_addr[t] = sAu + (wm + 16 * t + (lid & 15)) * (PKH * 2) + ((lid >> 4) << 4);
#pragma unroll
    for (int jj = 0; jj < 4; jj++)
        b_addr[jj] = sBu + (wn + 16 * jj + ((lid >> 4) << 3) + (lid & 7)) * (PKH * 2)
                   + (((lid >> 3) & 1) << 4);

#pragma unroll
    for (int t = 0; t < 2; t++)
#pragma unroll
        for (int j = 0; j < 8; j++)
#pragma unroll
            for (int c = 0; c < 4; c++) acc[t][j][c] = 0.f;

    // prologue: issue slabs 0..2 into stages 0..2 (one commit-group each)
#pragma unroll
    for (int p = 0; p < 3; p++) {
        const uint32_t so = (uint32_t)p * GEMM_STAGE_B;
        const int k0 = p * 32;
        cp_async16(dA0 + so, gA0 + k0);
        cp_async16(dA1 + so, gA1 + k0);
        cp_async16(dB0 + so, gB0 + k0);
        cp_async16(dB1 + so, gB1 + k0);
        CP_COMMIT();
    }

#pragma unroll 1
    for (int s = 0; s < NSLAB; s++) {
        CP_WAIT2();            // group s (slab s) complete
        __syncthreads();       // and all warps done with compute s-1

        if (s + 3 < NSLAB) {   // issue slab s+3 into stage (s+3)&3
            const uint32_t so = (uint32_t)((s + 3) & 3) * GEMM_STAGE_B;
            const int k0 = (s + 3) * 32;
            cp_async16(dA0 + so, gA0 + k0);
            cp_async16(dA1 + so, gA1 + k0);
            cp_async16(dB0 + so, gB0 + k0);
            cp_async16(dB1 + so, gB1 + k0);
        }
        CP_COMMIT();           // always commit (keeps group numbering fixed)

        const uint32_t soff = (uint32_t)(s & 3) * GEMM_STAGE_B;
#pragma unroll
        for (int ks = 0; ks < 2; ks++) {
            const uint32_t ko = soff + ks * 32;   // 16 halves = 32 B
            uint32_t a[2][4];
#pragma unroll
            for (int t = 0; t < 2; t++)
                ldmatrix_x4(a[t][0], a[t][1], a[t][2], a[t][3], a_addr[t] + ko);
            uint32_t b[8][2];
#pragma unroll
            for (int jj = 0; jj < 4; jj++) {
                uint32_t r0, r1, r2, r3;
                ldmatrix_x4(r0, r1, r2, r3, b_addr[jj] + ko);
                b[2 * jj][0] = r0;  b[2 * jj][1] = r1;
                b[2 * jj + 1][0] = r2;  b[2 * jj + 1][1] = r3;
            }
#pragma unroll
            for (int t = 0; t < 2; t++)
#pragma unroll
                for (int j = 0; j < 8; j++)
                    mma_f16(acc[t][j], a[t][0], a[t][1], a[t][2], a[t][3],
                            b[j][0], b[j][1]);
        }
    }
}

// QKV fused GEMM: z selects (W, bias, half-out). X = g_xh.
struct QKVArgs { const float *b0, *b1, *b2; __half *o0, *o1, *o2; };

__global__ void __launch_bounds__(256)
gemm_qkv_kernel(QKVArgs args)
{
    extern __shared__ __half dsm[];
    const int z = blockIdx.z;
    const float* bias = (z == 0) ? args.b0 : (z == 1) ? args.b1 : args.b2;
    __half* out       = (z == 0) ? args.o0 : (z == 1) ? args.o1 : args.o2;
    const int m0 = blockIdx.y * 128;
    const int n0 = blockIdx.x * 128;

    float acc[2][8][4];
    gemm_mainloop(g_xh, g_wh + (size_t)z * kC * kC, m0, n0, dsm, acc);

    const int lid = threadIdx.x & 31;
    const int wid = threadIdx.x >> 5;
    const int wm  = (wid >> 1) * 32;
    const int wn  = (wid & 1) * 64;
    const int g   = lid >> 2;
    const int cp  = (lid & 3) * 2;
#pragma unroll
    for (int t = 0; t < 2; t++) {
        const int r0 = m0 + wm + 16 * t + g;
#pragma unroll
        for (int j = 0; j < 8; j++) {
            const int n = n0 + wn + 8 * j + cp;
            const float bx = bias[n], by = bias[n + 1];
            *(uint32_t*)&out[(size_t)r0 * kC + n] =
                f2h2(acc[t][j][0] + bx, acc[t][j][1] + by);
            *(uint32_t*)&out[(size_t)(r0 + 8) * kC + n] =
                f2h2(acc[t][j][2] + bx, acc[t][j][3] + by);
        }
    }
}

// Output GEMM: X = g_ctx (half), W = Wo (converted), out fp32 + bias + skip.
__global__ void __launch_bounds__(256)
gemm_o_kernel(const float* __restrict__ bias, const float* __restrict__ skip,
              float* __restrict__ out)
{
    extern __shared__ __half dsm[];
    const int m0 = blockIdx.y * 128;
    const int n0 = blockIdx.x * 128;

    float acc[2][8][4];
    gemm_mainloop(g_ctx, g_wh + (size_t)3 * kC * kC, m0, n0, dsm, acc);

    const int lid = threadIdx.x & 31;
    const int wid = threadIdx.x >> 5;
    const int wm  = (wid >> 1) * 32;
    const int wn  = (wid & 1) * 64;
    const int g   = lid >> 2;
    const int cp  = (lid & 3) * 2;
#pragma unroll
    for (int t = 0; t < 2; t++) {
        const int r0 = m0 + wm + 16 * t + g;
#pragma unroll
        for (int j = 0; j < 8; j++) {
            const int n = n0 + wn + 8 * j + cp;
            const float bx = bias[n], by = bias[n + 1];
            float2 s0 = *(const float2*)&skip[(size_t)r0 * kC + n];
            float2 s1 = *(const float2*)&skip[(size_t)(r0 + 8) * kC + n];
            *(float2*)&out[(size_t)r0 * kC + n] =
                make_float2(acc[t][j][0] + bx + s0.x, acc[t][j][1] + by + s0.y);
            *(float2*)&out[(size_t)(r0 + 8) * kC + n] =
                make_float2(acc[t][j][2] + bx + s1.x, acc[t][j][3] + by + s1.y);
        }
    }
}

// ===========================================================================
// Tensor-core flash attention (f16 mma.sync, fp32 accumulate).
// CTA = 128 queries x one (b,h); 8 warps x 16 query rows; key tiles of 64.
// Q fragments hoisted to registers. P stays in registers (C->A repack).
// K/V tiles: 3-stage cp.async pipeline, wait_group 1, always-commit.
// smem (dynamic): 3 stages x (Ks[64][72] | Vs[64][72]) = 55296 B.
// ===========================================================================
namespace {
constexpr int PQH = 72;
constexpr int ATTN_TILE_B = 128 * PQH * 2;     // 18432 B per stage (K+V)
constexpr int ATTN_SMEM   = 3 * ATTN_TILE_B;   // 55296 B
constexpr int NTILE = kS / 64;                 // 16
}

__global__ void __launch_bounds__(256)
attn_tc_kernel()
{
    extern __shared__ __half sm[];

    const int tid = threadIdx.x;
    const int lid = tid & 31;
    const int wid = tid >> 5;
    const int b   = blockIdx.z;
    const int h   = blockIdx.y;
    const int q0  = blockIdx.x * 128;

    const __half* Qg = g_q + (size_t)(b * kS + q0) * kC + h * kDH;
    const __half* Kg = g_k + (size_t)(b * kS) * kC + h * kDH;
    const __half* Vg = g_v + (size_t)(b * kS) * kC + h * kDH;

    // --- Stage Q through smem once; extract loop-invariant A fragments ---
#pragma unroll
    for (int t = 0; t < 4; t++) {
        int idx = tid + t * 256;          // 0..1023 16B-chunks
        int row = idx >> 3;               // 0..127
        int c8  = (idx & 7) * 8;
        *(uint4*)&sm[row * PQH + c8] = *(const uint4*)(Qg + (size_t)row * kC + c8);
    }
    __syncthreads();
    uint32_t qf[4][4];
    {
        const uint32_t aq = smem_u32(sm)
            + (wid * 16 + (lid & 15)) * (PQH * 2) + ((lid >> 4) << 4);
#pragma unroll
        for (int ks = 0; ks < 4; ks++)
            ldmatrix_x4(qf[ks][0], qf[ks][1], qf[ks][2], qf[ks][3], aq + ks * 32);
    }
    __syncthreads();   // done with Q staging; smem now K/V stages

    // cp.async destinations (stage 0): K rows 0..63, V rows 64..127
    const int lrow = tid >> 3;            // 0..31
    const int lc8  = (tid & 7) * 8;
    const uint32_t smu = smem_u32(sm);
    const uint32_t dK0 = smu + (lrow * PQH + lc8) * 2;
    const uint32_t dK1 = dK0 + 32 * PQH * 2;
    const uint32_t dV0 = smu + ((64 + lrow) * PQH + lc8) * 2;
    const uint32_t dV1 = dV0 + 32 * PQH * 2;
    const __half* gK0 = Kg + (size_t)lrow * kC + lc8;
    const __half* gK1 = Kg + (size_t)(32 + lrow) * kC + lc8;
    const __half* gV0 = Vg + (size_t)lrow * kC + lc8;
    const __half* gV1 = Vg + (size_t)(32 + lrow) * kC + lc8;

    // fragment addresses (stage 0)
    uint32_t bk[4], bvb[4];
#pragma unroll
    for (int jj = 0; jj < 4; jj++) {
        bk[jj] = smu
            + (16 * jj + ((lid >> 4) << 3) + (lid & 7)) * (PQH * 2)
            + (((lid >> 3) & 1) << 4);
        bvb[jj] = smu + 64 * PQH * 2
            + ((((lid >> 3) & 1) << 3) + (lid & 7)) * (PQH * 2)
            + (((lid >> 4) + 2 * jj) << 4);
    }

    float m_i[2] = {-INFINITY, -INFINITY};
    float l_i[2] = {0.f, 0.f};
    float accO[8][4];
#pragma unroll
    for (int j = 0; j < 8; j++)
#pragma unroll
        for (int c = 0; c < 4; c++) accO[j][c] = 0.f;
    const float cexp = 0.125f * 1.4426950408889634f;  // scale * log2(e)

    const int pr = wid * 16 + (lid >> 2);
    const int pc = (lid & 3) * 2;

    // prologue: issue K/V tiles 0,1 into stages 0,1
#pragma unroll
    for (int p = 0; p < 2; p++) {
        const uint32_t so = (uint32_t)p * ATTN_TILE_B;
        const size_t go = (size_t)p * 64 * kC;
        cp_async16(dK0 + so, gK0 + go);
        cp_async16(dK1 + so, gK1 + go);
        cp_async16(dV0 + so, gV0 + go);
        cp_async16(dV1 + so, gV1 + go);
        CP_COMMIT();
    }

#pragma unroll 1
    for (int i = 0; i < NTILE; i++) {
        CP_WAIT1();            // group i (tile i) complete
        __syncthreads();       // all warps done with compute i-1

        if (i + 2 < NTILE) {   // issue tile i+2 into stage (i+2)%3
            const uint32_t so = (uint32_t)((i + 2) % 3) * ATTN_TILE_B;
            const size_t go = (size_t)(i + 2) * 64 * kC;
            cp_async16(dK0 + so, gK0 + go);
            cp_async16(dK1 + so, gK1 + go);
            cp_async16(dV0 + so, gV0 + go);
            cp_async16(dV1 + so, gV1 + go);
        }
        CP_COMMIT();           // always commit

        const uint32_t boff = (uint32_t)(i % 3) * ATTN_TILE_B;

        // S = Q K^T   (4 k16 steps over d=64)
        float s[8][4];
#pragma unroll
        for (int j = 0; j < 8; j++)
#pragma unroll
            for (int c = 0; c < 4; c++) s[j][c] = 0.f;
#pragma unroll
        for (int ks = 0; ks < 4; ks++) {
            uint32_t bf[8][2];
#pragma unroll
            for (int jj = 0; jj < 4; jj++) {
                uint32_t r0, r1, r2, r3;
                ldmatrix_x4(r0, r1, r2, r3, bk[jj] + boff + ks * 32);
                bf[2 * jj][0] = r0;  bf[2 * jj][1] = r1;
                bf[2 * jj + 1][0] = r2;  bf[2 * jj + 1][1] = r3;
            }
#pragma unroll
            for (int j = 0; j < 8; j++)
                mma_f16(s[j], qf[ks][0], qf[ks][1], qf[ks][2], qf[ks][3],
                        bf[j][0], bf[j][1]);
        }

        // online softmax (half 0: row pr; half 1: row pr+8)
#pragma unroll
        for (int hf = 0; hf < 2; hf++) {
            const int c0 = 2 * hf, c1 = 2 * hf + 1;
            float mx = fmaxf(s[0][c0], s[0][c1]);
#pragma unroll
            for (int j = 1; j < 8; j++)
                mx = fmaxf(mx, fmaxf(s[j][c0], s[j][c1]));
            mx = fmaxf(mx, __shfl_xor_sync(0xffffffffu, mx, 1));
            mx = fmaxf(mx, __shfl_xor_sync(0xffffffffu, mx, 2));
            float mnew = fmaxf(m_i[hf], mx);
            float alpha = exp2f((m_i[hf] - mnew) * cexp);
            float rs = 0.f;
#pragma unroll
            for (int j = 0; j < 8; j++) {
                s[j][c0] = exp2f((s[j][c0] - mnew) * cexp);
                s[j][c1] = exp2f((s[j][c1] - mnew) * cexp);
                rs += s[j][c0] + s[j][c1];
            }
            rs += __shfl_xor_sync(0xffffffffu, rs, 1);
            rs += __shfl_xor_sync(0xffffffffu, rs, 2);
            l_i[hf] = l_i[hf] * alpha + rs;
            m_i[hf] = mnew;
#pragma unroll
            for (int j = 0; j < 8; j++) {
                accO[j][c0] *= alpha;
                accO[j][c1] *= alpha;
            }
        }

        // O += P * V : P's A-fragments come straight from S's C-fragments.
#pragma unroll
        for (int ks = 0; ks < 4; ks++) {
            const uint32_t a0 = f2h2(s[2 * ks][0],     s[2 * ks][1]);
            const uint32_t a1 = f2h2(s[2 * ks][2],     s[2 * ks][3]);
            const uint32_t a2 = f2h2(s[2 * ks + 1][0], s[2 * ks + 1][1]);
            const uint32_t a3 = f2h2(s[2 * ks + 1][2], s[2 * ks + 1][3]);
            uint32_t bf[8][2];
#pragma unroll
            for (int jj = 0; jj < 4; jj++) {
                uint32_t r0, r1, r2, r3;
                ldmatrix_x4_trans(r0, r1, r2, r3,
                                  bvb[jj] + boff + ks * 16 * (PQH * 2));
                bf[2 * jj][0] = r0;  bf[2 * jj][1] = r1;
                bf[2 * jj + 1][0] = r2;  bf[2 * jj + 1][1] = r3;
            }
#pragma unroll
            for (int j = 0; j < 8; j++)
                mma_f16(accO[j], a0, a1, a2, a3, bf[j][0], bf[j][1]);
        }
    }

    // normalize + write ctx (fp16)
    {
        const float inv0 = 1.f / l_i[0];
        const float inv1 = 1.f / l_i[1];
        __half* O0 = g_ctx + (size_t)(b * kS + q0 + pr) * kC + h * kDH;
        __half* O1 = O0 + (size_t)8 * kC;
#pragma unroll
        for (int j = 0; j < 8; j++) {
            const int c = 8 * j + pc;
            *(uint32_t*)&O0[c] = f2h2(accO[j][0] * inv0, accO[j][1] * inv0);
            *(uint32_t*)&O1[c] = f2h2(accO[j][2] * inv1, accO[j][3] * inv1);
        }
    }
}

// ---------------------------------------------------------------------------
// Launch
// ---------------------------------------------------------------------------
extern "C" void kernel_launch(void* const* d_in, const int* in_sizes, int n_in,
                              void* d_out, int out_size)
{
    (void)in_sizes; (void)n_in; (void)out_size;
    const float* x    = (const float*)d_in[0];
    const float* skip = (const float*)d_in[1];
    const float* Wq   = (const float*)d_in[2];
    const float* bq   = (const float*)d_in[3];
    const float* Wk   = (const float*)d_in[4];
    const float* bk   = (const float*)d_in[5];
    const float* Wv   = (const float*)d_in[6];
    const float* bv   = (const float*)d_in[7];
    const float* Wo   = (const float*)d_in[8];
    const float* bo   = (const float*)d_in[9];
    float* out = (float*)d_out;

    __half *qb, *kb, *vb;
    cudaGetSymbolAddress((void**)&qb, g_q);
    cudaGetSymbolAddress((void**)&kb, g_k);
    cudaGetSymbolAddress((void**)&vb, g_v);

    cudaFuncSetAttribute(gemm_qkv_kernel,
                         cudaFuncAttributeMaxDynamicSharedMemorySize, GEMM_SMEM);
    cudaFuncSetAttribute(gemm_o_kernel,
                         cudaFuncAttributeMaxDynamicSharedMemorySize, GEMM_SMEM);
    cudaFuncSetAttribute(attn_tc_kernel,
                         cudaFuncAttributeMaxDynamicSharedMemorySize, ATTN_SMEM);

    // 1) convert x + weights to fp16
    CvtArgs ca; ca.src[0] = x; ca.src[1] = Wq; ca.src[2] = Wk;
    ca.src[3] = Wv; ca.src[4] = Wo;
    convert_kernel<<<(NX4 + 4 * NW4) / 256, 256>>>(ca);

    // 2) fused QKV projections (CTA tile 128x128, 4-stage pipeline)
    QKVArgs qkv = { bq, bk, bv, qb, kb, vb };
    gemm_qkv_kernel<<<dim3(kC / 128, kM / 128, 3), 256, GEMM_SMEM>>>(qkv);

    // 3) attention (3-stage pipeline)
    attn_tc_kernel<<<dim3(kS / 128, kH, kB), 256, ATTN_SMEM>>>();

    // 4) output projection + bias + skip
    gemm_o_kernel<<<dim3(kC / 128, kM / 128, 1), 256, GEMM_SMEM>>>(bo, skip, out);
}